// round 5
// baseline (speedup 1.0000x reference)
#include <cuda_runtime.h>
#include <math.h>

#define N_NODES 50000
#define E_EDGES 800000
#define ETOT    (E_EDGES + N_NODES)   // 850000
#define F_IN    128
#define HID     64
#define HEADS   4
#define C1      (HEADS * HID)         // 256
#define SLOPE   0.2f
#define EPS_SM  1e-16f

#define SCAN_T  1024
#define SCAN_CH 52                     // 52*1024 = 53248 >= N_NODES, /4
#define N_PAD   (SCAN_T * SCAN_CH)

// ------------------------- device scratch (no allocs allowed) ---------------
__device__ float g_h1  [(size_t)N_NODES * C1];    // x @ W1
__device__ float g_x2  [(size_t)N_NODES * C1];    // layer1 output after LN/ELU
__device__ float g_h2  [(size_t)N_NODES * HID];   // x2 @ W2
__device__ float g_s1  [N_NODES * HEADS];
__device__ float g_d1  [N_NODES * HEADS];
__device__ float g_s2  [N_NODES];
__device__ float g_d2  [N_NODES];
// CSR by destination (rebuilt every launch; deterministic work)
__device__ __align__(16) int g_cnt   [N_PAD];
__device__ __align__(16) int g_rowptr[N_PAD + 4];
__device__ __align__(16) int g_wofs  [N_PAD + 4];
__device__ int g_esrc  [ETOT];
__device__ int g_eid   [ETOT];
// fallback alpha scratch in case d_out layout differs from expectation
__device__ float g_a1_fb[(size_t)ETOT * HEADS];
__device__ float g_a2_fb[(size_t)ETOT];

// ------------------------- helpers ------------------------------------------
__device__ __forceinline__ float lrelu(float v) { return v > 0.f ? v : SLOPE * v; }
__device__ __forceinline__ float eluf(float v)  { return v > 0.f ? v : expm1f(v); }

__device__ __forceinline__ float wredsum(float v) {
#pragma unroll
    for (int o = 16; o > 0; o >>= 1) v += __shfl_xor_sync(0xffffffffu, v, o);
    return v;
}

// packed fp32x2 (sm_10x): one SASS FFMA2 = 2 FMA per issue slot
__device__ __forceinline__ unsigned long long packdup(float a) {
    unsigned long long r; unsigned int u = __float_as_uint(a);
    asm("mov.b64 %0, {%1, %1};" : "=l"(r) : "r"(u));
    return r;
}
__device__ __forceinline__ unsigned long long ffma2(unsigned long long a,
                                                    unsigned long long b,
                                                    unsigned long long c) {
    unsigned long long d;
    asm("fma.rn.f32x2 %0, %1, %2, %3;" : "=l"(d) : "l"(a), "l"(b), "l"(c));
    return d;
}
__device__ __forceinline__ float2 unpack2(unsigned long long p) {
    unsigned int lo, hi;
    asm("mov.b64 {%0, %1}, %2;" : "=r"(lo), "=r"(hi) : "l"(p));
    return make_float2(__uint_as_float(lo), __uint_as_float(hi));
}

// ------------------------- CSR build -----------------------------------------
__global__ void zero_cnt_kernel() {
    int i = blockIdx.x * blockDim.x + threadIdx.x;
    if (i < N_PAD / 4) *reinterpret_cast<int4*>(&g_cnt[i * 4]) = make_int4(0, 0, 0, 0);
}

__global__ void hist_kernel(const int* __restrict__ ei) {
    int i0 = (blockIdx.x * blockDim.x + threadIdx.x) * 4;
    if (i0 >= ETOT) return;
    if (i0 + 4 <= E_EDGES) {
        int4 d = *reinterpret_cast<const int4*>(&ei[E_EDGES + i0]);
        atomicAdd(&g_cnt[d.x], 1);
        atomicAdd(&g_cnt[d.y], 1);
        atomicAdd(&g_cnt[d.z], 1);
        atomicAdd(&g_cnt[d.w], 1);
    } else {
#pragma unroll
        for (int t = 0; t < 4; t++) {
            int e = i0 + t;
            if (e < ETOT) {
                int dst = (e < E_EDGES) ? ei[E_EDGES + e] : e - E_EDGES;
                atomicAdd(&g_cnt[dst], 1);
            }
        }
    }
}

__global__ __launch_bounds__(SCAN_T) void scan_kernel() {
    __shared__ int sums[SCAN_T];
    int t = threadIdx.x;
    int lo = t * SCAN_CH;
    const int4* cp = reinterpret_cast<const int4*>(&g_cnt[lo]);
    int local = 0;
#pragma unroll
    for (int i = 0; i < SCAN_CH / 4; i++) {
        int4 c = cp[i];
        local += c.x + c.y + c.z + c.w;
    }
    sums[t] = local;
    __syncthreads();
    for (int off = 1; off < SCAN_T; off <<= 1) {
        int v = (t >= off) ? sums[t - off] : 0;
        __syncthreads();
        sums[t] += v;
        __syncthreads();
    }
    int run = sums[t] - local;                    // exclusive prefix
    int4* rp = reinterpret_cast<int4*>(&g_rowptr[lo]);
    int4* wp = reinterpret_cast<int4*>(&g_wofs[lo]);
#pragma unroll
    for (int i = 0; i < SCAN_CH / 4; i++) {
        int4 c = cp[i];
        int4 o;
        o.x = run; run += c.x;
        o.y = run; run += c.y;
        o.z = run; run += c.z;
        o.w = run; run += c.w;
        rp[i] = o; wp[i] = o;
    }
}

__global__ void scatter_kernel(const int* __restrict__ ei) {
    int i0 = (blockIdx.x * blockDim.x + threadIdx.x) * 4;
    if (i0 >= ETOT) return;
    if (i0 + 4 <= E_EDGES) {
        int4 s = *reinterpret_cast<const int4*>(&ei[i0]);
        int4 d = *reinterpret_cast<const int4*>(&ei[E_EDGES + i0]);
        int sl;
        sl = atomicAdd(&g_wofs[d.x], 1); g_esrc[sl] = s.x; g_eid[sl] = i0;
        sl = atomicAdd(&g_wofs[d.y], 1); g_esrc[sl] = s.y; g_eid[sl] = i0 + 1;
        sl = atomicAdd(&g_wofs[d.z], 1); g_esrc[sl] = s.z; g_eid[sl] = i0 + 2;
        sl = atomicAdd(&g_wofs[d.w], 1); g_esrc[sl] = s.w; g_eid[sl] = i0 + 3;
    } else {
#pragma unroll
        for (int t = 0; t < 4; t++) {
            int e = i0 + t;
            if (e < ETOT) {
                int src, dst;
                if (e < E_EDGES) { src = ei[e]; dst = ei[E_EDGES + e]; }
                else             { src = dst = e - E_EDGES; }
                int slot = atomicAdd(&g_wofs[dst], 1);
                g_esrc[slot] = src;
                g_eid[slot]  = e;
            }
        }
    }
}

// ---- GEMM (packed f32x2) + fused per-node attention logits -------------------
// Y[r, :] = X[r, :K] @ W[K, NCOLS];  S[r,h] = Y(r,head h) . asrc;  D likewise.
// thread tile: 4 rows x 8 cols. COLG = NCOLS/8 threads across cols.
template<int K, int NCOLS, int COLG, int ROWG, int NHEADS>
__global__ __launch_bounds__(COLG * ROWG)
void gemm_sd_kernel(const float* __restrict__ X, const float* __restrict__ W,
                    float* __restrict__ Y,
                    const float* __restrict__ asrc, const float* __restrict__ adst,
                    float* __restrict__ Sout, float* __restrict__ Dout, int nrows) {
    constexpr int TM = ROWG * 4;
    constexpr int NT = COLG * ROWG;
    __shared__ float xs[TM * K];
    __shared__ float ssm[TM][NHEADS];
    __shared__ float dsm[TM][NHEADS];

    int tid     = threadIdx.x;
    int rowbase = blockIdx.x * TM;
    for (int i = tid; i < TM * NHEADS; i += NT) {
        (&ssm[0][0])[i] = 0.f; (&dsm[0][0])[i] = 0.f;
    }
    for (int i = tid; i < TM * K; i += NT) {
        int r = i / K, c = i - r * K;
        int gr = rowbase + r;
        xs[i] = (gr < nrows) ? X[(size_t)gr * K + c] : 0.f;
    }
    __syncthreads();

    int tx = tid % COLG, ty = tid / COLG;
    int c0 = tx * 8;
    unsigned long long acc[4][4];
#pragma unroll
    for (int i = 0; i < 4; i++)
#pragma unroll
        for (int j = 0; j < 4; j++) acc[i][j] = 0ull;

#pragma unroll 4
    for (int k = 0; k < K; k++) {
        const ulonglong2* wp = reinterpret_cast<const ulonglong2*>(&W[(size_t)k * NCOLS + c0]);
        ulonglong2 w01 = wp[0];
        ulonglong2 w23 = wp[1];
#pragma unroll
        for (int i = 0; i < 4; i++) {
            unsigned long long ap = packdup(xs[(ty * 4 + i) * K + k]);
            acc[i][0] = ffma2(ap, w01.x, acc[i][0]);
            acc[i][1] = ffma2(ap, w01.y, acc[i][1]);
            acc[i][2] = ffma2(ap, w23.x, acc[i][2]);
            acc[i][3] = ffma2(ap, w23.y, acc[i][3]);
        }
    }

    // attention vectors for this thread's 8 columns (one head: 8 | 64)
    int h = (NHEADS == 1) ? 0 : (c0 >> 6);
    float4 as0 = *reinterpret_cast<const float4*>(&asrc[c0]);
    float4 as1 = *reinterpret_cast<const float4*>(&asrc[c0 + 4]);
    float4 ad0 = *reinterpret_cast<const float4*>(&adst[c0]);
    float4 ad1 = *reinterpret_cast<const float4*>(&adst[c0 + 4]);

#pragma unroll
    for (int i = 0; i < 4; i++) {
        int gr = rowbase + ty * 4 + i;
        float2 p0 = unpack2(acc[i][0]);
        float2 p1 = unpack2(acc[i][1]);
        float2 p2 = unpack2(acc[i][2]);
        float2 p3 = unpack2(acc[i][3]);
        if (gr < nrows) {
            float4* yp = reinterpret_cast<float4*>(&Y[(size_t)gr * NCOLS + c0]);
            yp[0] = make_float4(p0.x, p0.y, p1.x, p1.y);
            yp[1] = make_float4(p2.x, p2.y, p3.x, p3.y);
        }
        float ps = p0.x * as0.x + p0.y * as0.y + p1.x * as0.z + p1.y * as0.w
                 + p2.x * as1.x + p2.y * as1.y + p3.x * as1.z + p3.y * as1.w;
        float pd = p0.x * ad0.x + p0.y * ad0.y + p1.x * ad0.z + p1.y * ad0.w
                 + p2.x * ad1.x + p2.y * ad1.y + p3.x * ad1.z + p3.y * ad1.w;
        atomicAdd(&ssm[ty * 4 + i][h], ps);
        atomicAdd(&dsm[ty * 4 + i][h], pd);
    }
    __syncthreads();
    for (int i = tid; i < TM * NHEADS; i += NT) {
        int r = i / NHEADS, hh = i - r * NHEADS;
        int gr = rowbase + r;
        if (gr < nrows) {
            Sout[gr * NHEADS + hh] = ssm[r][hh];
            Dout[gr * NHEADS + hh] = dsm[r][hh];
        }
    }
}

// ------------------------- layer 1: single-pass gather + LN + ELU ------------
// one warp per destination node; acc holds the full 256-wide row (8 per lane)
__global__ __launch_bounds__(256)
void agg1_kernel(float* __restrict__ a1, const float* __restrict__ b1,
                 const float* __restrict__ gam, const float* __restrict__ bet) {
    int n    = (blockIdx.x * blockDim.x + threadIdx.x) >> 5;
    int lane = threadIdx.x & 31;
    if (n >= N_NODES) return;
    int base = g_rowptr[n], end = g_rowptr[n + 1];
    float4 d = *reinterpret_cast<const float4*>(&g_d1[n * 4]);

    int h  = lane >> 3;           // head for this lane's 8-feature slice
    int c0 = lane * 8;
    float acc[8];
#pragma unroll
    for (int i = 0; i < 8; i++) acc[i] = 0.f;
    float4 den = make_float4(0.f, 0.f, 0.f, 0.f);

    // single pass: unnormalized accumulate (2-edge unroll for MLP)
    int j = base;
    for (; j + 1 < end; j += 2) {
        int src0 = g_esrc[j], src1 = g_esrc[j + 1];
        float4 s0 = *reinterpret_cast<const float4*>(&g_s1[src0 * 4]);
        float4 s1 = *reinterpret_cast<const float4*>(&g_s1[src1 * 4]);
        const float4* hp0 = reinterpret_cast<const float4*>(&g_h1[(size_t)src0 * C1 + c0]);
        const float4* hp1 = reinterpret_cast<const float4*>(&g_h1[(size_t)src1 * C1 + c0]);
        float4 e0, e1;
        e0.x = __expf(lrelu(s0.x + d.x)); e0.y = __expf(lrelu(s0.y + d.y));
        e0.z = __expf(lrelu(s0.z + d.z)); e0.w = __expf(lrelu(s0.w + d.w));
        e1.x = __expf(lrelu(s1.x + d.x)); e1.y = __expf(lrelu(s1.y + d.y));
        e1.z = __expf(lrelu(s1.z + d.z)); e1.w = __expf(lrelu(s1.w + d.w));
        den.x += e0.x + e1.x; den.y += e0.y + e1.y;
        den.z += e0.z + e1.z; den.w += e0.w + e1.w;
        float a0 = (h == 0) ? e0.x : (h == 1) ? e0.y : (h == 2) ? e0.z : e0.w;
        float a1w = (h == 0) ? e1.x : (h == 1) ? e1.y : (h == 2) ? e1.z : e1.w;
        float4 v00 = hp0[0], v01 = hp0[1];
        float4 v10 = hp1[0], v11 = hp1[1];
        acc[0] += v00.x * a0 + v10.x * a1w; acc[1] += v00.y * a0 + v10.y * a1w;
        acc[2] += v00.z * a0 + v10.z * a1w; acc[3] += v00.w * a0 + v10.w * a1w;
        acc[4] += v01.x * a0 + v11.x * a1w; acc[5] += v01.y * a0 + v11.y * a1w;
        acc[6] += v01.z * a0 + v11.z * a1w; acc[7] += v01.w * a0 + v11.w * a1w;
    }
    if (j < end) {
        int src = g_esrc[j];
        float4 s = *reinterpret_cast<const float4*>(&g_s1[src * 4]);
        float4 e;
        e.x = __expf(lrelu(s.x + d.x)); e.y = __expf(lrelu(s.y + d.y));
        e.z = __expf(lrelu(s.z + d.z)); e.w = __expf(lrelu(s.w + d.w));
        den.x += e.x; den.y += e.y; den.z += e.z; den.w += e.w;
        float a = (h == 0) ? e.x : (h == 1) ? e.y : (h == 2) ? e.z : e.w;
        const float4* hp = reinterpret_cast<const float4*>(&g_h1[(size_t)src * C1 + c0]);
        float4 v0 = hp[0], v1 = hp[1];
        acc[0] += v0.x * a; acc[1] += v0.y * a; acc[2] += v0.z * a; acc[3] += v0.w * a;
        acc[4] += v1.x * a; acc[5] += v1.y * a; acc[6] += v1.z * a; acc[7] += v1.w * a;
    }

    float4 inv = make_float4(1.f / (den.x + EPS_SM), 1.f / (den.y + EPS_SM),
                             1.f / (den.z + EPS_SM), 1.f / (den.w + EPS_SM));

    // alpha writes, lane-parallel
    for (int jj = base + lane; jj < end; jj += 32) {
        int src = g_esrc[jj];
        float4 s = *reinterpret_cast<const float4*>(&g_s1[src * 4]);
        float4 al;
        al.x = __expf(lrelu(s.x + d.x)) * inv.x;
        al.y = __expf(lrelu(s.y + d.y)) * inv.y;
        al.z = __expf(lrelu(s.z + d.z)) * inv.z;
        al.w = __expf(lrelu(s.w + d.w)) * inv.w;
        *reinterpret_cast<float4*>(&a1[(size_t)g_eid[jj] * 4]) = al;
    }

    // normalize this lane's head slice
    float invh = (h == 0) ? inv.x : (h == 1) ? inv.y : (h == 2) ? inv.z : inv.w;
#pragma unroll
    for (int i = 0; i < 8; i++) acc[i] *= invh;

    // epilogue: +b1, LayerNorm(256), ELU -> g_x2
    float4 ba = *reinterpret_cast<const float4*>(&b1[c0]);
    float4 bb = *reinterpret_cast<const float4*>(&b1[c0 + 4]);
    acc[0] += ba.x; acc[1] += ba.y; acc[2] += ba.z; acc[3] += ba.w;
    acc[4] += bb.x; acc[5] += bb.y; acc[6] += bb.z; acc[7] += bb.w;
    float sum = 0.f, sq = 0.f;
#pragma unroll
    for (int i = 0; i < 8; i++) { sum += acc[i]; sq += acc[i] * acc[i]; }
    sum = wredsum(sum); sq = wredsum(sq);
    float mu  = sum * (1.f / 256.f);
    float var = sq * (1.f / 256.f) - mu * mu;
    float rs  = rsqrtf(var + 1e-5f);
    float4 ga = *reinterpret_cast<const float4*>(&gam[c0]);
    float4 gb = *reinterpret_cast<const float4*>(&gam[c0 + 4]);
    float4 ea = *reinterpret_cast<const float4*>(&bet[c0]);
    float4 eb = *reinterpret_cast<const float4*>(&bet[c0 + 4]);
    float4 y0, y1;
    y0.x = eluf((acc[0] - mu) * rs * ga.x + ea.x);
    y0.y = eluf((acc[1] - mu) * rs * ga.y + ea.y);
    y0.z = eluf((acc[2] - mu) * rs * ga.z + ea.z);
    y0.w = eluf((acc[3] - mu) * rs * ga.w + ea.w);
    y1.x = eluf((acc[4] - mu) * rs * gb.x + eb.x);
    y1.y = eluf((acc[5] - mu) * rs * gb.y + eb.y);
    y1.z = eluf((acc[6] - mu) * rs * gb.z + eb.z);
    y1.w = eluf((acc[7] - mu) * rs * gb.w + eb.w);
    float4* orow = reinterpret_cast<float4*>(&g_x2[(size_t)n * C1 + c0]);
    orow[0] = y0; orow[1] = y1;
}

// ------------------------- layer 2: single-pass gather + LN + ELU + head -----
__global__ __launch_bounds__(256)
void agg2_kernel(float* __restrict__ a2, const float* __restrict__ b2,
                 const float* __restrict__ g2, const float* __restrict__ e2,
                 const float* __restrict__ hW1, const float* __restrict__ hb1,
                 const float* __restrict__ hW2, const float* __restrict__ hb2,
                 float* __restrict__ out) {
    __shared__ float w1s[64 * 32];
    __shared__ float w2s[32];
    __shared__ float b1s[32];
    __shared__ float zs[8][64];
    int tid = threadIdx.x;
    for (int i = tid; i < 64 * 32; i += 256) w1s[i] = hW1[i];
    if (tid < 32) { w2s[tid] = hW2[tid]; b1s[tid] = hb1[tid]; }
    __syncthreads();

    int w    = tid >> 5;
    int lane = tid & 31;
    int n = blockIdx.x * 8 + w;
    if (n >= N_NODES) return;

    int base = g_rowptr[n], end = g_rowptr[n + 1];
    float dd = g_d2[n];

    float a0 = 0.f, a1v = 0.f, den = 0.f;
    int c0 = lane * 2;
    int j = base;
    for (; j + 1 < end; j += 2) {
        int src0 = g_esrc[j], src1 = g_esrc[j + 1];
        float e0 = __expf(lrelu(g_s2[src0] + dd));
        float e1 = __expf(lrelu(g_s2[src1] + dd));
        float2 v0 = *reinterpret_cast<const float2*>(&g_h2[(size_t)src0 * HID + c0]);
        float2 v1 = *reinterpret_cast<const float2*>(&g_h2[(size_t)src1 * HID + c0]);
        den += e0 + e1;
        a0  += v0.x * e0 + v1.x * e1;
        a1v += v0.y * e0 + v1.y * e1;
    }
    if (j < end) {
        int src = g_esrc[j];
        float e = __expf(lrelu(g_s2[src] + dd));
        float2 v = *reinterpret_cast<const float2*>(&g_h2[(size_t)src * HID + c0]);
        den += e; a0 += v.x * e; a1v += v.y * e;
    }
    float inv = 1.f / (den + EPS_SM);

    for (int jj = base + lane; jj < end; jj += 32) {
        int src = g_esrc[jj];
        a2[g_eid[jj]] = __expf(lrelu(g_s2[src] + dd)) * inv;
    }
    a0 *= inv; a1v *= inv;

    // +b2, LN(64), ELU
    a0  += b2[c0];
    a1v += b2[c0 + 1];
    float sum = wredsum(a0 + a1v);
    float sq  = wredsum(a0 * a0 + a1v * a1v);
    float mu  = sum * (1.f / 64.f);
    float var = sq * (1.f / 64.f) - mu * mu;
    float rs  = rsqrtf(var + 1e-5f);
    float y0 = eluf((a0  - mu) * rs * g2[c0]     + e2[c0]);
    float y1 = eluf((a1v - mu) * rs * g2[c0 + 1] + e2[c0 + 1]);
    zs[w][c0] = y0; zs[w][c0 + 1] = y1;
    __syncwarp();

    // MLP head: 64 -> 32 -> ReLU -> 1
    float acc = b1s[lane];
#pragma unroll
    for (int k = 0; k < 64; k++) acc += zs[w][k] * w1s[k * 32 + lane];
    acc = fmaxf(acc, 0.f);
    float p = wredsum(acc * w2s[lane]);
    if (lane == 0) out[n] = p + hb2[0];
}

// ------------------------- host launcher -------------------------------------
extern "C" void kernel_launch(void* const* d_in, const int* in_sizes, int n_in,
                              void* d_out, int out_size) {
    const float* x     = (const float*)d_in[0];
    const int*   ei    = (const int*)  d_in[1];
    const float* W1    = (const float*)d_in[2];
    const float* as1   = (const float*)d_in[3];
    const float* ad1   = (const float*)d_in[4];
    const float* b1    = (const float*)d_in[5];
    const float* W2    = (const float*)d_in[6];
    const float* as2   = (const float*)d_in[7];
    const float* ad2   = (const float*)d_in[8];
    const float* b2    = (const float*)d_in[9];
    const float* ln1g  = (const float*)d_in[10];
    const float* ln1b  = (const float*)d_in[11];
    const float* ln2g  = (const float*)d_in[12];
    const float* ln2b  = (const float*)d_in[13];
    const float* hW1   = (const float*)d_in[14];
    const float* hb1   = (const float*)d_in[15];
    const float* hW2   = (const float*)d_in[16];
    const float* hb2   = (const float*)d_in[17];
    float* out = (float*)d_out;

    // expected layout: out[N] | alpha1[ETOT*4] | alpha2[ETOT]
    size_t need = (size_t)N_NODES + (size_t)ETOT * (HEADS + 1);
    float *a1, *a2;
    if ((size_t)out_size >= need) {
        a1 = out + N_NODES;
        a2 = a1 + (size_t)ETOT * HEADS;
    } else {
        void* p;
        cudaGetSymbolAddress(&p, g_a1_fb); a1 = (float*)p;
        cudaGetSymbolAddress(&p, g_a2_fb); a2 = (float*)p;
    }

    auto cdiv = [](long a, long b) { return (int)((a + b - 1) / b); };

    float *ph1, *px2, *ph2, *ps1, *pd1, *ps2, *pd2;
    { void* p;
      cudaGetSymbolAddress(&p, g_h1); ph1 = (float*)p;
      cudaGetSymbolAddress(&p, g_x2); px2 = (float*)p;
      cudaGetSymbolAddress(&p, g_h2); ph2 = (float*)p;
      cudaGetSymbolAddress(&p, g_s1); ps1 = (float*)p;
      cudaGetSymbolAddress(&p, g_d1); pd1 = (float*)p;
      cudaGetSymbolAddress(&p, g_s2); ps2 = (float*)p;
      cudaGetSymbolAddress(&p, g_d2); pd2 = (float*)p;
    }

    // ---- CSR build (reused by both layers) ----
    zero_cnt_kernel<<<cdiv(N_PAD / 4, 256), 256>>>();
    hist_kernel<<<cdiv(cdiv(ETOT, 4), 256), 256>>>(ei);
    scan_kernel<<<1, SCAN_T>>>();
    scatter_kernel<<<cdiv(cdiv(ETOT, 4), 256), 256>>>(ei);

    // ---- layer 1: GEMM(f32x2) + fused logits ----
    gemm_sd_kernel<128, 256, 32, 8, 4><<<cdiv(N_NODES, 32), 256>>>(
        x, W1, ph1, as1, ad1, ps1, pd1, N_NODES);
    agg1_kernel<<<cdiv((long)N_NODES * 32, 256), 256>>>(a1, b1, ln1g, ln1b);

    // ---- layer 2: GEMM(f32x2) + fused logits ----
    gemm_sd_kernel<256, 64, 8, 8, 1><<<cdiv(N_NODES, 32), 64>>>(
        px2, W2, ph2, as2, ad2, ps2, pd2, N_NODES);
    agg2_kernel<<<cdiv(N_NODES, 8), 256>>>(a2, b2, ln2g, ln2b, hW1, hb1, hW2, hb2, out);
}

// round 6
// speedup vs baseline: 1.7181x; 1.7181x over previous
#include <cuda_runtime.h>
#include <math.h>

#define N_NODES 50000
#define E_EDGES 800000
#define ETOT    (E_EDGES + N_NODES)   // 850000
#define F_IN    128
#define HID     64
#define HEADS   4
#define C1      (HEADS * HID)         // 256
#define SLOPE   0.2f
#define EPS_SM  1e-16f

#define SCAN_T  1024
#define SCAN_CH 52                     // 52*1024 = 53248 >= N_NODES, /4
#define N_PAD   (SCAN_T * SCAN_CH)

// ------------------------- device scratch (no allocs allowed) ---------------
__device__ float g_h1  [(size_t)N_NODES * C1];    // x @ W1
__device__ float g_x2  [(size_t)N_NODES * C1];    // layer1 output after LN/ELU
__device__ float g_h2  [(size_t)N_NODES * HID];   // x2 @ W2
__device__ float g_s1  [N_NODES * HEADS];
__device__ float g_d1  [N_NODES * HEADS];
__device__ float g_s2  [N_NODES];
__device__ float g_d2  [N_NODES];
// CSR by destination (rebuilt every launch; deterministic work)
__device__ __align__(16) int g_cnt   [N_PAD];
__device__ __align__(16) int g_rowptr[N_PAD + 4];
__device__ __align__(16) int g_wofs  [N_PAD + 4];
__device__ int g_esrc  [ETOT];
__device__ int g_eid   [ETOT];
// fallback alpha scratch in case d_out layout differs from expectation
__device__ float g_a1_fb[(size_t)ETOT * HEADS];
__device__ float g_a2_fb[(size_t)ETOT];

// ------------------------- helpers ------------------------------------------
__device__ __forceinline__ float lrelu(float v) { return v > 0.f ? v : SLOPE * v; }
__device__ __forceinline__ float eluf(float v)  { return v > 0.f ? v : expm1f(v); }

__device__ __forceinline__ float wredsum(float v) {
#pragma unroll
    for (int o = 16; o > 0; o >>= 1) v += __shfl_xor_sync(0xffffffffu, v, o);
    return v;
}

// ------------------------- CSR build -----------------------------------------
__global__ void zero_cnt_kernel() {
    int i = blockIdx.x * blockDim.x + threadIdx.x;
    if (i < N_PAD / 4) *reinterpret_cast<int4*>(&g_cnt[i * 4]) = make_int4(0, 0, 0, 0);
}

__global__ void hist_kernel(const int* __restrict__ ei) {
    int i0 = (blockIdx.x * blockDim.x + threadIdx.x) * 4;
    if (i0 >= ETOT) return;
    if (i0 + 4 <= E_EDGES) {
        int4 d = *reinterpret_cast<const int4*>(&ei[E_EDGES + i0]);
        atomicAdd(&g_cnt[d.x], 1);
        atomicAdd(&g_cnt[d.y], 1);
        atomicAdd(&g_cnt[d.z], 1);
        atomicAdd(&g_cnt[d.w], 1);
    } else {
#pragma unroll
        for (int t = 0; t < 4; t++) {
            int e = i0 + t;
            if (e < ETOT) {
                int dst = (e < E_EDGES) ? ei[E_EDGES + e] : e - E_EDGES;
                atomicAdd(&g_cnt[dst], 1);
            }
        }
    }
}

__global__ __launch_bounds__(SCAN_T) void scan_kernel() {
    __shared__ int sums[SCAN_T];
    int t = threadIdx.x;
    int lo = t * SCAN_CH;
    const int4* cp = reinterpret_cast<const int4*>(&g_cnt[lo]);
    int local = 0;
#pragma unroll
    for (int i = 0; i < SCAN_CH / 4; i++) {
        int4 c = cp[i];
        local += c.x + c.y + c.z + c.w;
    }
    sums[t] = local;
    __syncthreads();
    for (int off = 1; off < SCAN_T; off <<= 1) {
        int v = (t >= off) ? sums[t - off] : 0;
        __syncthreads();
        sums[t] += v;
        __syncthreads();
    }
    int run = sums[t] - local;                    // exclusive prefix
    int4* rp = reinterpret_cast<int4*>(&g_rowptr[lo]);
    int4* wp = reinterpret_cast<int4*>(&g_wofs[lo]);
#pragma unroll
    for (int i = 0; i < SCAN_CH / 4; i++) {
        int4 c = cp[i];
        int4 o;
        o.x = run; run += c.x;
        o.y = run; run += c.y;
        o.z = run; run += c.z;
        o.w = run; run += c.w;
        rp[i] = o; wp[i] = o;
    }
}

__global__ void scatter_kernel(const int* __restrict__ ei) {
    int i0 = (blockIdx.x * blockDim.x + threadIdx.x) * 4;
    if (i0 >= ETOT) return;
    if (i0 + 4 <= E_EDGES) {
        int4 s = *reinterpret_cast<const int4*>(&ei[i0]);
        int4 d = *reinterpret_cast<const int4*>(&ei[E_EDGES + i0]);
        int sl;
        sl = atomicAdd(&g_wofs[d.x], 1); g_esrc[sl] = s.x; g_eid[sl] = i0;
        sl = atomicAdd(&g_wofs[d.y], 1); g_esrc[sl] = s.y; g_eid[sl] = i0 + 1;
        sl = atomicAdd(&g_wofs[d.z], 1); g_esrc[sl] = s.z; g_eid[sl] = i0 + 2;
        sl = atomicAdd(&g_wofs[d.w], 1); g_esrc[sl] = s.w; g_eid[sl] = i0 + 3;
    } else {
#pragma unroll
        for (int t = 0; t < 4; t++) {
            int e = i0 + t;
            if (e < ETOT) {
                int src, dst;
                if (e < E_EDGES) { src = ei[e]; dst = ei[E_EDGES + e]; }
                else             { src = dst = e - E_EDGES; }
                int slot = atomicAdd(&g_wofs[dst], 1);
                g_esrc[slot] = src;
                g_eid[slot]  = e;
            }
        }
    }
}

// ------------------------- GEMM: Y[r, 0:NCOLS] = X[r, 0:K] @ W[K, NCOLS] ----
// (R4 plain-FFMA version — the f32x2 variant regressed 2x; reverted)
template<int K, int NCOLS, int COLG, int ROWG>
__global__ __launch_bounds__(COLG * ROWG)
void gemm_kernel(const float* __restrict__ X, const float* __restrict__ W,
                 float* __restrict__ Y, int nrows) {
    constexpr int TM = ROWG * 4;
    constexpr int NT = COLG * ROWG;
    __shared__ float xs[TM * K];

    int tid     = threadIdx.x;
    int rowbase = blockIdx.x * TM;
    for (int i = tid; i < TM * K; i += NT) {
        int r = i / K, c = i - r * K;
        int gr = rowbase + r;
        xs[i] = (gr < nrows) ? X[(size_t)gr * K + c] : 0.f;
    }
    __syncthreads();

    int tx = tid % COLG, ty = tid / COLG;
    int c0 = tx * 4;
    float acc[4][4];
#pragma unroll
    for (int i = 0; i < 4; i++)
#pragma unroll
        for (int j = 0; j < 4; j++) acc[i][j] = 0.f;

#pragma unroll 4
    for (int k = 0; k < K; k++) {
        float4 w = *reinterpret_cast<const float4*>(&W[(size_t)k * NCOLS + c0]);
#pragma unroll
        for (int i = 0; i < 4; i++) {
            float a = xs[(ty * 4 + i) * K + k];
            acc[i][0] += a * w.x; acc[i][1] += a * w.y;
            acc[i][2] += a * w.z; acc[i][3] += a * w.w;
        }
    }
#pragma unroll
    for (int i = 0; i < 4; i++) {
        int gr = rowbase + ty * 4 + i;
        if (gr < nrows)
            *reinterpret_cast<float4*>(&Y[(size_t)gr * NCOLS + c0]) =
                make_float4(acc[i][0], acc[i][1], acc[i][2], acc[i][3]);
    }
}

// ------------------------- per-node attention logits ------------------------
__global__ void sd1_kernel(const float* __restrict__ asrc, const float* __restrict__ adst) {
    int idx = blockIdx.x * blockDim.x + threadIdx.x;
    if (idx >= N_NODES * HEADS) return;
    int n = idx >> 2, h = idx & 3;
    const float4* hp = reinterpret_cast<const float4*>(&g_h1[(size_t)n * C1 + h * HID]);
    const float4* as = reinterpret_cast<const float4*>(&asrc[h * HID]);
    const float4* ad = reinterpret_cast<const float4*>(&adst[h * HID]);
    float ss = 0.f, dd = 0.f;
#pragma unroll
    for (int i = 0; i < HID / 4; i++) {
        float4 v = hp[i], a = as[i], b = ad[i];
        ss += v.x * a.x + v.y * a.y + v.z * a.z + v.w * a.w;
        dd += v.x * b.x + v.y * b.y + v.z * b.z + v.w * b.w;
    }
    g_s1[idx] = ss; g_d1[idx] = dd;
}

__global__ void sd2_kernel(const float* __restrict__ asrc, const float* __restrict__ adst) {
    int n = blockIdx.x * blockDim.x + threadIdx.x;
    if (n >= N_NODES) return;
    const float4* hp = reinterpret_cast<const float4*>(&g_h2[(size_t)n * HID]);
    const float4* as = reinterpret_cast<const float4*>(asrc);
    const float4* ad = reinterpret_cast<const float4*>(adst);
    float ss = 0.f, dd = 0.f;
#pragma unroll
    for (int i = 0; i < HID / 4; i++) {
        float4 v = hp[i], a = as[i], b = ad[i];
        ss += v.x * a.x + v.y * a.y + v.z * a.z + v.w * a.w;
        dd += v.x * b.x + v.y * b.y + v.z * b.z + v.w * b.w;
    }
    g_s2[n] = ss; g_d2[n] = dd;
}

// ------------------------- layer 1: single-pass gather + LN + ELU ------------
// one warp per destination node; acc holds the full 256-wide row (8 per lane)
__global__ __launch_bounds__(256)
void agg1_kernel(float* __restrict__ a1, const float* __restrict__ b1,
                 const float* __restrict__ gam, const float* __restrict__ bet) {
    int n    = (blockIdx.x * blockDim.x + threadIdx.x) >> 5;
    int lane = threadIdx.x & 31;
    if (n >= N_NODES) return;
    int base = g_rowptr[n], end = g_rowptr[n + 1];
    float4 d = *reinterpret_cast<const float4*>(&g_d1[n * 4]);

    int h  = lane >> 3;           // head for this lane's 8-feature slice
    int c0 = lane * 8;
    float acc[8];
#pragma unroll
    for (int i = 0; i < 8; i++) acc[i] = 0.f;
    float4 den = make_float4(0.f, 0.f, 0.f, 0.f);

    // single pass: unnormalized accumulate (2-edge unroll for MLP)
    int j = base;
    for (; j + 1 < end; j += 2) {
        int src0 = g_esrc[j], src1 = g_esrc[j + 1];
        float4 s0 = *reinterpret_cast<const float4*>(&g_s1[src0 * 4]);
        float4 s1 = *reinterpret_cast<const float4*>(&g_s1[src1 * 4]);
        const float4* hp0 = reinterpret_cast<const float4*>(&g_h1[(size_t)src0 * C1 + c0]);
        const float4* hp1 = reinterpret_cast<const float4*>(&g_h1[(size_t)src1 * C1 + c0]);
        float4 e0, e1;
        e0.x = __expf(lrelu(s0.x + d.x)); e0.y = __expf(lrelu(s0.y + d.y));
        e0.z = __expf(lrelu(s0.z + d.z)); e0.w = __expf(lrelu(s0.w + d.w));
        e1.x = __expf(lrelu(s1.x + d.x)); e1.y = __expf(lrelu(s1.y + d.y));
        e1.z = __expf(lrelu(s1.z + d.z)); e1.w = __expf(lrelu(s1.w + d.w));
        den.x += e0.x + e1.x; den.y += e0.y + e1.y;
        den.z += e0.z + e1.z; den.w += e0.w + e1.w;
        float a0 = (h == 0) ? e0.x : (h == 1) ? e0.y : (h == 2) ? e0.z : e0.w;
        float a1w = (h == 0) ? e1.x : (h == 1) ? e1.y : (h == 2) ? e1.z : e1.w;
        float4 v00 = hp0[0], v01 = hp0[1];
        float4 v10 = hp1[0], v11 = hp1[1];
        acc[0] += v00.x * a0 + v10.x * a1w; acc[1] += v00.y * a0 + v10.y * a1w;
        acc[2] += v00.z * a0 + v10.z * a1w; acc[3] += v00.w * a0 + v10.w * a1w;
        acc[4] += v01.x * a0 + v11.x * a1w; acc[5] += v01.y * a0 + v11.y * a1w;
        acc[6] += v01.z * a0 + v11.z * a1w; acc[7] += v01.w * a0 + v11.w * a1w;
    }
    if (j < end) {
        int src = g_esrc[j];
        float4 s = *reinterpret_cast<const float4*>(&g_s1[src * 4]);
        float4 e;
        e.x = __expf(lrelu(s.x + d.x)); e.y = __expf(lrelu(s.y + d.y));
        e.z = __expf(lrelu(s.z + d.z)); e.w = __expf(lrelu(s.w + d.w));
        den.x += e.x; den.y += e.y; den.z += e.z; den.w += e.w;
        float a = (h == 0) ? e.x : (h == 1) ? e.y : (h == 2) ? e.z : e.w;
        const float4* hp = reinterpret_cast<const float4*>(&g_h1[(size_t)src * C1 + c0]);
        float4 v0 = hp[0], v1 = hp[1];
        acc[0] += v0.x * a; acc[1] += v0.y * a; acc[2] += v0.z * a; acc[3] += v0.w * a;
        acc[4] += v1.x * a; acc[5] += v1.y * a; acc[6] += v1.z * a; acc[7] += v1.w * a;
    }

    float4 inv = make_float4(1.f / (den.x + EPS_SM), 1.f / (den.y + EPS_SM),
                             1.f / (den.z + EPS_SM), 1.f / (den.w + EPS_SM));

    // alpha writes, lane-parallel
    for (int jj = base + lane; jj < end; jj += 32) {
        int src = g_esrc[jj];
        float4 s = *reinterpret_cast<const float4*>(&g_s1[src * 4]);
        float4 al;
        al.x = __expf(lrelu(s.x + d.x)) * inv.x;
        al.y = __expf(lrelu(s.y + d.y)) * inv.y;
        al.z = __expf(lrelu(s.z + d.z)) * inv.z;
        al.w = __expf(lrelu(s.w + d.w)) * inv.w;
        *reinterpret_cast<float4*>(&a1[(size_t)g_eid[jj] * 4]) = al;
    }

    // normalize this lane's head slice
    float invh = (h == 0) ? inv.x : (h == 1) ? inv.y : (h == 2) ? inv.z : inv.w;
#pragma unroll
    for (int i = 0; i < 8; i++) acc[i] *= invh;

    // epilogue: +b1, LayerNorm(256), ELU -> g_x2
    float4 ba = *reinterpret_cast<const float4*>(&b1[c0]);
    float4 bb = *reinterpret_cast<const float4*>(&b1[c0 + 4]);
    acc[0] += ba.x; acc[1] += ba.y; acc[2] += ba.z; acc[3] += ba.w;
    acc[4] += bb.x; acc[5] += bb.y; acc[6] += bb.z; acc[7] += bb.w;
    float sum = 0.f, sq = 0.f;
#pragma unroll
    for (int i = 0; i < 8; i++) { sum += acc[i]; sq += acc[i] * acc[i]; }
    sum = wredsum(sum); sq = wredsum(sq);
    float mu  = sum * (1.f / 256.f);
    float var = sq * (1.f / 256.f) - mu * mu;
    float rs  = rsqrtf(var + 1e-5f);
    float4 ga = *reinterpret_cast<const float4*>(&gam[c0]);
    float4 gb = *reinterpret_cast<const float4*>(&gam[c0 + 4]);
    float4 ea = *reinterpret_cast<const float4*>(&bet[c0]);
    float4 eb = *reinterpret_cast<const float4*>(&bet[c0 + 4]);
    float4 y0, y1;
    y0.x = eluf((acc[0] - mu) * rs * ga.x + ea.x);
    y0.y = eluf((acc[1] - mu) * rs * ga.y + ea.y);
    y0.z = eluf((acc[2] - mu) * rs * ga.z + ea.z);
    y0.w = eluf((acc[3] - mu) * rs * ga.w + ea.w);
    y1.x = eluf((acc[4] - mu) * rs * gb.x + eb.x);
    y1.y = eluf((acc[5] - mu) * rs * gb.y + eb.y);
    y1.z = eluf((acc[6] - mu) * rs * gb.z + eb.z);
    y1.w = eluf((acc[7] - mu) * rs * gb.w + eb.w);
    float4* orow = reinterpret_cast<float4*>(&g_x2[(size_t)n * C1 + c0]);
    orow[0] = y0; orow[1] = y1;
}

// ------------------------- layer 2: single-pass gather + LN + ELU + head -----
__global__ __launch_bounds__(256)
void agg2_kernel(float* __restrict__ a2, const float* __restrict__ b2,
                 const float* __restrict__ g2, const float* __restrict__ e2,
                 const float* __restrict__ hW1, const float* __restrict__ hb1,
                 const float* __restrict__ hW2, const float* __restrict__ hb2,
                 float* __restrict__ out) {
    __shared__ float w1s[64 * 32];
    __shared__ float w2s[32];
    __shared__ float b1s[32];
    __shared__ float zs[8][64];
    int tid = threadIdx.x;
    for (int i = tid; i < 64 * 32; i += 256) w1s[i] = hW1[i];
    if (tid < 32) { w2s[tid] = hW2[tid]; b1s[tid] = hb1[tid]; }
    __syncthreads();

    int w    = tid >> 5;
    int lane = tid & 31;
    int n = blockIdx.x * 8 + w;
    if (n >= N_NODES) return;

    int base = g_rowptr[n], end = g_rowptr[n + 1];
    float dd = g_d2[n];

    float a0 = 0.f, a1v = 0.f, den = 0.f;
    int c0 = lane * 2;
    int j = base;
    for (; j + 1 < end; j += 2) {
        int src0 = g_esrc[j], src1 = g_esrc[j + 1];
        float e0 = __expf(lrelu(g_s2[src0] + dd));
        float e1 = __expf(lrelu(g_s2[src1] + dd));
        float2 v0 = *reinterpret_cast<const float2*>(&g_h2[(size_t)src0 * HID + c0]);
        float2 v1 = *reinterpret_cast<const float2*>(&g_h2[(size_t)src1 * HID + c0]);
        den += e0 + e1;
        a0  += v0.x * e0 + v1.x * e1;
        a1v += v0.y * e0 + v1.y * e1;
    }
    if (j < end) {
        int src = g_esrc[j];
        float e = __expf(lrelu(g_s2[src] + dd));
        float2 v = *reinterpret_cast<const float2*>(&g_h2[(size_t)src * HID + c0]);
        den += e; a0 += v.x * e; a1v += v.y * e;
    }
    float inv = 1.f / (den + EPS_SM);

    for (int jj = base + lane; jj < end; jj += 32) {
        int src = g_esrc[jj];
        a2[g_eid[jj]] = __expf(lrelu(g_s2[src] + dd)) * inv;
    }
    a0 *= inv; a1v *= inv;

    // +b2, LN(64), ELU
    a0  += b2[c0];
    a1v += b2[c0 + 1];
    float sum = wredsum(a0 + a1v);
    float sq  = wredsum(a0 * a0 + a1v * a1v);
    float mu  = sum * (1.f / 64.f);
    float var = sq * (1.f / 64.f) - mu * mu;
    float rs  = rsqrtf(var + 1e-5f);
    float y0 = eluf((a0  - mu) * rs * g2[c0]     + e2[c0]);
    float y1 = eluf((a1v - mu) * rs * g2[c0 + 1] + e2[c0 + 1]);
    zs[w][c0] = y0; zs[w][c0 + 1] = y1;
    __syncwarp();

    // MLP head: 64 -> 32 -> ReLU -> 1
    float acc = b1s[lane];
#pragma unroll
    for (int k = 0; k < 64; k++) acc += zs[w][k] * w1s[k * 32 + lane];
    acc = fmaxf(acc, 0.f);
    float p = wredsum(acc * w2s[lane]);
    if (lane == 0) out[n] = p + hb2[0];
}

// ------------------------- host launcher -------------------------------------
extern "C" void kernel_launch(void* const* d_in, const int* in_sizes, int n_in,
                              void* d_out, int out_size) {
    const float* x     = (const float*)d_in[0];
    const int*   ei    = (const int*)  d_in[1];
    const float* W1    = (const float*)d_in[2];
    const float* as1   = (const float*)d_in[3];
    const float* ad1   = (const float*)d_in[4];
    const float* b1    = (const float*)d_in[5];
    const float* W2    = (const float*)d_in[6];
    const float* as2   = (const float*)d_in[7];
    const float* ad2   = (const float*)d_in[8];
    const float* b2    = (const float*)d_in[9];
    const float* ln1g  = (const float*)d_in[10];
    const float* ln1b  = (const float*)d_in[11];
    const float* ln2g  = (const float*)d_in[12];
    const float* ln2b  = (const float*)d_in[13];
    const float* hW1   = (const float*)d_in[14];
    const float* hb1   = (const float*)d_in[15];
    const float* hW2   = (const float*)d_in[16];
    const float* hb2   = (const float*)d_in[17];
    float* out = (float*)d_out;

    // expected layout: out[N] | alpha1[ETOT*4] | alpha2[ETOT]
    size_t need = (size_t)N_NODES + (size_t)ETOT * (HEADS + 1);
    float *a1, *a2;
    if ((size_t)out_size >= need) {
        a1 = out + N_NODES;
        a2 = a1 + (size_t)ETOT * HEADS;
    } else {
        void* p;
        cudaGetSymbolAddress(&p, g_a1_fb); a1 = (float*)p;
        cudaGetSymbolAddress(&p, g_a2_fb); a2 = (float*)p;
    }

    auto cdiv = [](long a, long b) { return (int)((a + b - 1) / b); };

    float *ph1, *px2, *ph2;
    { void* p;
      cudaGetSymbolAddress(&p, g_h1); ph1 = (float*)p;
      cudaGetSymbolAddress(&p, g_x2); px2 = (float*)p;
      cudaGetSymbolAddress(&p, g_h2); ph2 = (float*)p;
    }

    // ---- CSR build (reused by both layers) ----
    zero_cnt_kernel<<<cdiv(N_PAD / 4, 256), 256>>>();
    hist_kernel<<<cdiv(cdiv(ETOT, 4), 256), 256>>>(ei);
    scan_kernel<<<1, SCAN_T>>>();
    scatter_kernel<<<cdiv(cdiv(ETOT, 4), 256), 256>>>(ei);

    // ---- layer 1 ----
    gemm_kernel<128, 256, 64, 4><<<cdiv(N_NODES, 16), 256>>>(x, W1, ph1, N_NODES);
    sd1_kernel<<<cdiv(N_NODES * HEADS, 256), 256>>>(as1, ad1);
    agg1_kernel<<<cdiv((long)N_NODES * 32, 256), 256>>>(a1, b1, ln1g, ln1b);

    // ---- layer 2 ----
    gemm_kernel<256, 64, 16, 8><<<cdiv(N_NODES, 32), 128>>>(px2, W2, ph2, N_NODES);
    sd2_kernel<<<cdiv(N_NODES, 256), 256>>>(as2, ad2);
    agg2_kernel<<<cdiv(N_NODES, 8), 256>>>(a2, b2, ln2g, ln2b, hW1, hb1, hW2, hb2, out);
}

// round 7
// speedup vs baseline: 1.8799x; 1.0942x over previous
#include <cuda_runtime.h>
#include <math.h>

#define N_NODES 50000
#define E_EDGES 800000
#define ETOT    (E_EDGES + N_NODES)   // 850000
#define F_IN    128
#define HID     64
#define HEADS   4
#define C1      (HEADS * HID)         // 256
#define SLOPE   0.2f
#define EPS_SM  1e-16f

#define SCAN_T  1024
#define SCAN_CH 52                     // 52*1024 = 53248 >= N_NODES, /4
#define N_PAD   (SCAN_T * SCAN_CH)

// ------------------------- device scratch (no allocs allowed) ---------------
__device__ float g_h1  [(size_t)N_NODES * C1];    // x @ W1
__device__ float g_x2  [(size_t)N_NODES * C1];    // layer1 output after LN/ELU
__device__ float g_h2  [(size_t)N_NODES * HID];   // x2 @ W2
__device__ float g_s1  [N_NODES * HEADS];
__device__ float g_d1  [N_NODES * HEADS];
__device__ float g_s2  [N_NODES];
__device__ float g_d2  [N_NODES];
// CSR by destination (rebuilt every launch; deterministic work)
__device__ __align__(16) int g_cnt   [N_PAD];
__device__ __align__(16) int g_rowptr[N_PAD + 4];
__device__ __align__(16) int g_wofs  [N_PAD + 4];
__device__ int2 g_epack[ETOT];                    // {src, eid} per CSR slot
// fallback alpha scratch in case d_out layout differs from expectation
__device__ float g_a1_fb[(size_t)ETOT * HEADS];
__device__ float g_a2_fb[(size_t)ETOT];

// ------------------------- helpers ------------------------------------------
__device__ __forceinline__ float lrelu(float v) { return v > 0.f ? v : SLOPE * v; }
__device__ __forceinline__ float eluf(float v)  { return v > 0.f ? v : expm1f(v); }

__device__ __forceinline__ float wredsum(float v) {
#pragma unroll
    for (int o = 16; o > 0; o >>= 1) v += __shfl_xor_sync(0xffffffffu, v, o);
    return v;
}

// ------------------------- CSR build -----------------------------------------
__global__ void zero_cnt_kernel() {
    int i = blockIdx.x * blockDim.x + threadIdx.x;
    if (i < N_PAD / 4) *reinterpret_cast<int4*>(&g_cnt[i * 4]) = make_int4(0, 0, 0, 0);
}

__global__ void hist_kernel(const int* __restrict__ ei) {
    int i0 = (blockIdx.x * blockDim.x + threadIdx.x) * 4;
    if (i0 >= ETOT) return;
    if (i0 + 4 <= E_EDGES) {
        int4 d = *reinterpret_cast<const int4*>(&ei[E_EDGES + i0]);
        atomicAdd(&g_cnt[d.x], 1);
        atomicAdd(&g_cnt[d.y], 1);
        atomicAdd(&g_cnt[d.z], 1);
        atomicAdd(&g_cnt[d.w], 1);
    } else {
#pragma unroll
        for (int t = 0; t < 4; t++) {
            int e = i0 + t;
            if (e < ETOT) {
                int dst = (e < E_EDGES) ? ei[E_EDGES + e] : e - E_EDGES;
                atomicAdd(&g_cnt[dst], 1);
            }
        }
    }
}

__global__ __launch_bounds__(SCAN_T) void scan_kernel() {
    __shared__ int sums[SCAN_T];
    int t = threadIdx.x;
    int lo = t * SCAN_CH;
    const int4* cp = reinterpret_cast<const int4*>(&g_cnt[lo]);
    int local = 0;
#pragma unroll
    for (int i = 0; i < SCAN_CH / 4; i++) {
        int4 c = cp[i];
        local += c.x + c.y + c.z + c.w;
    }
    sums[t] = local;
    __syncthreads();
    for (int off = 1; off < SCAN_T; off <<= 1) {
        int v = (t >= off) ? sums[t - off] : 0;
        __syncthreads();
        sums[t] += v;
        __syncthreads();
    }
    int run = sums[t] - local;                    // exclusive prefix
    int4* rp = reinterpret_cast<int4*>(&g_rowptr[lo]);
    int4* wp = reinterpret_cast<int4*>(&g_wofs[lo]);
#pragma unroll
    for (int i = 0; i < SCAN_CH / 4; i++) {
        int4 c = cp[i];
        int4 o;
        o.x = run; run += c.x;
        o.y = run; run += c.y;
        o.z = run; run += c.z;
        o.w = run; run += c.w;
        rp[i] = o; wp[i] = o;
    }
}

__global__ void scatter_kernel(const int* __restrict__ ei) {
    int i0 = (blockIdx.x * blockDim.x + threadIdx.x) * 4;
    if (i0 >= ETOT) return;
    if (i0 + 4 <= E_EDGES) {
        int4 s = *reinterpret_cast<const int4*>(&ei[i0]);
        int4 d = *reinterpret_cast<const int4*>(&ei[E_EDGES + i0]);
        int sl;
        sl = atomicAdd(&g_wofs[d.x], 1); g_epack[sl] = make_int2(s.x, i0);
        sl = atomicAdd(&g_wofs[d.y], 1); g_epack[sl] = make_int2(s.y, i0 + 1);
        sl = atomicAdd(&g_wofs[d.z], 1); g_epack[sl] = make_int2(s.z, i0 + 2);
        sl = atomicAdd(&g_wofs[d.w], 1); g_epack[sl] = make_int2(s.w, i0 + 3);
    } else {
#pragma unroll
        for (int t = 0; t < 4; t++) {
            int e = i0 + t;
            if (e < ETOT) {
                int src, dst;
                if (e < E_EDGES) { src = ei[e]; dst = ei[E_EDGES + e]; }
                else             { src = dst = e - E_EDGES; }
                int slot = atomicAdd(&g_wofs[dst], 1);
                g_epack[slot] = make_int2(src, e);
            }
        }
    }
}

// ---- layer-1 GEMM + fused logits --------------------------------------------
// Y = X[.,128] @ W1[128,256]; S/D[gr,h] via 16-lane shuffle reduce.
// threads 256: tx=tid%64 (col group of 4), ty=tid/64 (row group of 4). TM=16.
__global__ __launch_bounds__(256)
void gemm_sd1_kernel(const float* __restrict__ X, const float* __restrict__ W,
                     float* __restrict__ Y,
                     const float* __restrict__ asrc, const float* __restrict__ adst,
                     float* __restrict__ S, float* __restrict__ D, int nrows) {
    constexpr int K = 128, NCOLS = 256, TM = 16, NT = 256;
    __shared__ float xs[TM * K];

    int tid     = threadIdx.x;
    int rowbase = blockIdx.x * TM;
    for (int i = tid; i < TM * K; i += NT) {
        int r = i / K, c = i - r * K;
        int gr = rowbase + r;
        xs[i] = (gr < nrows) ? X[(size_t)gr * K + c] : 0.f;
    }
    __syncthreads();

    int tx = tid % 64, ty = tid / 64;
    int c0 = tx * 4;
    float acc[4][4];
#pragma unroll
    for (int i = 0; i < 4; i++)
#pragma unroll
        for (int j = 0; j < 4; j++) acc[i][j] = 0.f;

#pragma unroll 4
    for (int k = 0; k < K; k++) {
        float4 w = *reinterpret_cast<const float4*>(&W[(size_t)k * NCOLS + c0]);
#pragma unroll
        for (int i = 0; i < 4; i++) {
            float a = xs[(ty * 4 + i) * K + k];
            acc[i][0] += a * w.x; acc[i][1] += a * w.y;
            acc[i][2] += a * w.z; acc[i][3] += a * w.w;
        }
    }

    float4 av = *reinterpret_cast<const float4*>(&asrc[c0]);
    float4 dv = *reinterpret_cast<const float4*>(&adst[c0]);
    int lane = tid & 31;
    int h0   = 2 * ((tid >> 5) & 1);    // warp covers heads h0, h0+1

#pragma unroll
    for (int i = 0; i < 4; i++) {
        int gr = rowbase + ty * 4 + i;
        if (gr < nrows)
            *reinterpret_cast<float4*>(&Y[(size_t)gr * NCOLS + c0]) =
                make_float4(acc[i][0], acc[i][1], acc[i][2], acc[i][3]);
        float ps = acc[i][0] * av.x + acc[i][1] * av.y + acc[i][2] * av.z + acc[i][3] * av.w;
        float pd = acc[i][0] * dv.x + acc[i][1] * dv.y + acc[i][2] * dv.z + acc[i][3] * dv.w;
#pragma unroll
        for (int o = 8; o > 0; o >>= 1) {
            ps += __shfl_xor_sync(0xffffffffu, ps, o);
            pd += __shfl_xor_sync(0xffffffffu, pd, o);
        }
        if (gr < nrows) {
            if (lane == 0)  { S[gr * 4 + h0]     = ps; D[gr * 4 + h0]     = pd; }
            if (lane == 16) { S[gr * 4 + h0 + 1] = ps; D[gr * 4 + h0 + 1] = pd; }
        }
    }
}

// ---- layer-2 GEMM + fused logits --------------------------------------------
// Y = X[.,256] @ W2[256,64]; threads 128: tx=tid%16, ty=tid/16. TM=32.
__global__ __launch_bounds__(128)
void gemm_sd2_kernel(const float* __restrict__ X, const float* __restrict__ W,
                     float* __restrict__ Y,
                     const float* __restrict__ asrc, const float* __restrict__ adst,
                     float* __restrict__ S, float* __restrict__ D, int nrows) {
    constexpr int K = 256, NCOLS = 64, TM = 32, NT = 128;
    __shared__ float xs[TM * K];

    int tid     = threadIdx.x;
    int rowbase = blockIdx.x * TM;
    for (int i = tid; i < TM * K; i += NT) {
        int r = i / K, c = i - r * K;
        int gr = rowbase + r;
        xs[i] = (gr < nrows) ? X[(size_t)gr * K + c] : 0.f;
    }
    __syncthreads();

    int tx = tid % 16, ty = tid / 16;
    int c0 = tx * 4;
    float acc[4][4];
#pragma unroll
    for (int i = 0; i < 4; i++)
#pragma unroll
        for (int j = 0; j < 4; j++) acc[i][j] = 0.f;

#pragma unroll 4
    for (int k = 0; k < K; k++) {
        float4 w = *reinterpret_cast<const float4*>(&W[(size_t)k * NCOLS + c0]);
#pragma unroll
        for (int i = 0; i < 4; i++) {
            float a = xs[(ty * 4 + i) * K + k];
            acc[i][0] += a * w.x; acc[i][1] += a * w.y;
            acc[i][2] += a * w.z; acc[i][3] += a * w.w;
        }
    }

    float4 av = *reinterpret_cast<const float4*>(&asrc[c0]);
    float4 dv = *reinterpret_cast<const float4*>(&adst[c0]);
    int lane = tid & 31;

#pragma unroll
    for (int i = 0; i < 4; i++) {
        int gr = rowbase + ty * 4 + i;
        if (gr < nrows)
            *reinterpret_cast<float4*>(&Y[(size_t)gr * NCOLS + c0]) =
                make_float4(acc[i][0], acc[i][1], acc[i][2], acc[i][3]);
        float ps = acc[i][0] * av.x + acc[i][1] * av.y + acc[i][2] * av.z + acc[i][3] * av.w;
        float pd = acc[i][0] * dv.x + acc[i][1] * dv.y + acc[i][2] * dv.z + acc[i][3] * dv.w;
#pragma unroll
        for (int o = 8; o > 0; o >>= 1) {
            ps += __shfl_xor_sync(0xffffffffu, ps, o);
            pd += __shfl_xor_sync(0xffffffffu, pd, o);
        }
        if (gr < nrows && (lane == 0 || lane == 16)) { S[gr] = ps; D[gr] = pd; }
    }
}

// ------------------------- layer 1: single-pass gather + LN + ELU ------------
__global__ __launch_bounds__(256)
void agg1_kernel(float* __restrict__ a1, const float* __restrict__ b1,
                 const float* __restrict__ gam, const float* __restrict__ bet) {
    int n    = (blockIdx.x * blockDim.x + threadIdx.x) >> 5;
    int lane = threadIdx.x & 31;
    if (n >= N_NODES) return;
    int base = g_rowptr[n], end = g_rowptr[n + 1];
    float4 d = *reinterpret_cast<const float4*>(&g_d1[n * 4]);

    int h  = lane >> 3;           // head for this lane's 8-feature slice
    int c0 = lane * 8;
    float acc[8];
#pragma unroll
    for (int i = 0; i < 8; i++) acc[i] = 0.f;
    float4 den = make_float4(0.f, 0.f, 0.f, 0.f);

    int j = base;
    for (; j + 1 < end; j += 2) {
        int2 p0 = g_epack[j], p1 = g_epack[j + 1];
        int src0 = p0.x, src1 = p1.x;
        float4 s0 = *reinterpret_cast<const float4*>(&g_s1[src0 * 4]);
        float4 s1 = *reinterpret_cast<const float4*>(&g_s1[src1 * 4]);
        const float4* hp0 = reinterpret_cast<const float4*>(&g_h1[(size_t)src0 * C1 + c0]);
        const float4* hp1 = reinterpret_cast<const float4*>(&g_h1[(size_t)src1 * C1 + c0]);
        float4 e0, e1;
        e0.x = __expf(lrelu(s0.x + d.x)); e0.y = __expf(lrelu(s0.y + d.y));
        e0.z = __expf(lrelu(s0.z + d.z)); e0.w = __expf(lrelu(s0.w + d.w));
        e1.x = __expf(lrelu(s1.x + d.x)); e1.y = __expf(lrelu(s1.y + d.y));
        e1.z = __expf(lrelu(s1.z + d.z)); e1.w = __expf(lrelu(s1.w + d.w));
        den.x += e0.x + e1.x; den.y += e0.y + e1.y;
        den.z += e0.z + e1.z; den.w += e0.w + e1.w;
        float a0 = (h == 0) ? e0.x : (h == 1) ? e0.y : (h == 2) ? e0.z : e0.w;
        float a1w = (h == 0) ? e1.x : (h == 1) ? e1.y : (h == 2) ? e1.z : e1.w;
        float4 v00 = hp0[0], v01 = hp0[1];
        float4 v10 = hp1[0], v11 = hp1[1];
        acc[0] += v00.x * a0 + v10.x * a1w; acc[1] += v00.y * a0 + v10.y * a1w;
        acc[2] += v00.z * a0 + v10.z * a1w; acc[3] += v00.w * a0 + v10.w * a1w;
        acc[4] += v01.x * a0 + v11.x * a1w; acc[5] += v01.y * a0 + v11.y * a1w;
        acc[6] += v01.z * a0 + v11.z * a1w; acc[7] += v01.w * a0 + v11.w * a1w;
    }
    if (j < end) {
        int2 p = g_epack[j];
        int src = p.x;
        float4 s = *reinterpret_cast<const float4*>(&g_s1[src * 4]);
        float4 e;
        e.x = __expf(lrelu(s.x + d.x)); e.y = __expf(lrelu(s.y + d.y));
        e.z = __expf(lrelu(s.z + d.z)); e.w = __expf(lrelu(s.w + d.w));
        den.x += e.x; den.y += e.y; den.z += e.z; den.w += e.w;
        float a = (h == 0) ? e.x : (h == 1) ? e.y : (h == 2) ? e.z : e.w;
        const float4* hp = reinterpret_cast<const float4*>(&g_h1[(size_t)src * C1 + c0]);
        float4 v0 = hp[0], v1 = hp[1];
        acc[0] += v0.x * a; acc[1] += v0.y * a; acc[2] += v0.z * a; acc[3] += v0.w * a;
        acc[4] += v1.x * a; acc[5] += v1.y * a; acc[6] += v1.z * a; acc[7] += v1.w * a;
    }

    float4 inv = make_float4(1.f / (den.x + EPS_SM), 1.f / (den.y + EPS_SM),
                             1.f / (den.z + EPS_SM), 1.f / (den.w + EPS_SM));

    // alpha writes, lane-parallel
    for (int jj = base + lane; jj < end; jj += 32) {
        int2 p = g_epack[jj];
        float4 s = *reinterpret_cast<const float4*>(&g_s1[p.x * 4]);
        float4 al;
        al.x = __expf(lrelu(s.x + d.x)) * inv.x;
        al.y = __expf(lrelu(s.y + d.y)) * inv.y;
        al.z = __expf(lrelu(s.z + d.z)) * inv.z;
        al.w = __expf(lrelu(s.w + d.w)) * inv.w;
        *reinterpret_cast<float4*>(&a1[(size_t)p.y * 4]) = al;
    }

    float invh = (h == 0) ? inv.x : (h == 1) ? inv.y : (h == 2) ? inv.z : inv.w;
#pragma unroll
    for (int i = 0; i < 8; i++) acc[i] *= invh;

    // epilogue: +b1, LayerNorm(256), ELU -> g_x2
    float4 ba = *reinterpret_cast<const float4*>(&b1[c0]);
    float4 bb = *reinterpret_cast<const float4*>(&b1[c0 + 4]);
    acc[0] += ba.x; acc[1] += ba.y; acc[2] += ba.z; acc[3] += ba.w;
    acc[4] += bb.x; acc[5] += bb.y; acc[6] += bb.z; acc[7] += bb.w;
    float sum = 0.f, sq = 0.f;
#pragma unroll
    for (int i = 0; i < 8; i++) { sum += acc[i]; sq += acc[i] * acc[i]; }
    sum = wredsum(sum); sq = wredsum(sq);
    float mu  = sum * (1.f / 256.f);
    float var = sq * (1.f / 256.f) - mu * mu;
    float rs  = rsqrtf(var + 1e-5f);
    float4 ga = *reinterpret_cast<const float4*>(&gam[c0]);
    float4 gb = *reinterpret_cast<const float4*>(&gam[c0 + 4]);
    float4 ea = *reinterpret_cast<const float4*>(&bet[c0]);
    float4 eb = *reinterpret_cast<const float4*>(&bet[c0 + 4]);
    float4 y0, y1;
    y0.x = eluf((acc[0] - mu) * rs * ga.x + ea.x);
    y0.y = eluf((acc[1] - mu) * rs * ga.y + ea.y);
    y0.z = eluf((acc[2] - mu) * rs * ga.z + ea.z);
    y0.w = eluf((acc[3] - mu) * rs * ga.w + ea.w);
    y1.x = eluf((acc[4] - mu) * rs * gb.x + eb.x);
    y1.y = eluf((acc[5] - mu) * rs * gb.y + eb.y);
    y1.z = eluf((acc[6] - mu) * rs * gb.z + eb.z);
    y1.w = eluf((acc[7] - mu) * rs * gb.w + eb.w);
    float4* orow = reinterpret_cast<float4*>(&g_x2[(size_t)n * C1 + c0]);
    orow[0] = y0; orow[1] = y1;
}

// ------------------------- layer 2: single-pass gather + LN + ELU + head -----
__global__ __launch_bounds__(256)
void agg2_kernel(float* __restrict__ a2, const float* __restrict__ b2,
                 const float* __restrict__ g2, const float* __restrict__ e2,
                 const float* __restrict__ hW1, const float* __restrict__ hb1,
                 const float* __restrict__ hW2, const float* __restrict__ hb2,
                 float* __restrict__ out) {
    __shared__ float w1s[64 * 32];
    __shared__ float w2s[32];
    __shared__ float b1s[32];
    __shared__ float zs[8][64];
    int tid = threadIdx.x;
    for (int i = tid; i < 64 * 32; i += 256) w1s[i] = hW1[i];
    if (tid < 32) { w2s[tid] = hW2[tid]; b1s[tid] = hb1[tid]; }
    __syncthreads();

    int w    = tid >> 5;
    int lane = tid & 31;
    int n = blockIdx.x * 8 + w;
    if (n >= N_NODES) return;

    int base = g_rowptr[n], end = g_rowptr[n + 1];
    float dd = g_d2[n];

    float a0 = 0.f, a1v = 0.f, den = 0.f;
    int c0 = lane * 2;
    int j = base;
    for (; j + 1 < end; j += 2) {
        int2 p0 = g_epack[j], p1 = g_epack[j + 1];
        float e0 = __expf(lrelu(g_s2[p0.x] + dd));
        float e1 = __expf(lrelu(g_s2[p1.x] + dd));
        float2 v0 = *reinterpret_cast<const float2*>(&g_h2[(size_t)p0.x * HID + c0]);
        float2 v1 = *reinterpret_cast<const float2*>(&g_h2[(size_t)p1.x * HID + c0]);
        den += e0 + e1;
        a0  += v0.x * e0 + v1.x * e1;
        a1v += v0.y * e0 + v1.y * e1;
    }
    if (j < end) {
        int2 p = g_epack[j];
        float e = __expf(lrelu(g_s2[p.x] + dd));
        float2 v = *reinterpret_cast<const float2*>(&g_h2[(size_t)p.x * HID + c0]);
        den += e; a0 += v.x * e; a1v += v.y * e;
    }
    float inv = 1.f / (den + EPS_SM);

    for (int jj = base + lane; jj < end; jj += 32) {
        int2 p = g_epack[jj];
        a2[p.y] = __expf(lrelu(g_s2[p.x] + dd)) * inv;
    }
    a0 *= inv; a1v *= inv;

    // +b2, LN(64), ELU
    a0  += b2[c0];
    a1v += b2[c0 + 1];
    float sum = wredsum(a0 + a1v);
    float sq  = wredsum(a0 * a0 + a1v * a1v);
    float mu  = sum * (1.f / 64.f);
    float var = sq * (1.f / 64.f) - mu * mu;
    float rs  = rsqrtf(var + 1e-5f);
    float y0 = eluf((a0  - mu) * rs * g2[c0]     + e2[c0]);
    float y1 = eluf((a1v - mu) * rs * g2[c0 + 1] + e2[c0 + 1]);
    zs[w][c0] = y0; zs[w][c0 + 1] = y1;
    __syncwarp();

    // MLP head: 64 -> 32 -> ReLU -> 1
    float acc = b1s[lane];
#pragma unroll
    for (int k = 0; k < 64; k++) acc += zs[w][k] * w1s[k * 32 + lane];
    acc = fmaxf(acc, 0.f);
    float p = wredsum(acc * w2s[lane]);
    if (lane == 0) out[n] = p + hb2[0];
}

// ------------------------- host launcher -------------------------------------
extern "C" void kernel_launch(void* const* d_in, const int* in_sizes, int n_in,
                              void* d_out, int out_size) {
    const float* x     = (const float*)d_in[0];
    const int*   ei    = (const int*)  d_in[1];
    const float* W1    = (const float*)d_in[2];
    const float* as1   = (const float*)d_in[3];
    const float* ad1   = (const float*)d_in[4];
    const float* b1    = (const float*)d_in[5];
    const float* W2    = (const float*)d_in[6];
    const float* as2   = (const float*)d_in[7];
    const float* ad2   = (const float*)d_in[8];
    const float* b2    = (const float*)d_in[9];
    const float* ln1g  = (const float*)d_in[10];
    const float* ln1b  = (const float*)d_in[11];
    const float* ln2g  = (const float*)d_in[12];
    const float* ln2b  = (const float*)d_in[13];
    const float* hW1   = (const float*)d_in[14];
    const float* hb1   = (const float*)d_in[15];
    const float* hW2   = (const float*)d_in[16];
    const float* hb2   = (const float*)d_in[17];
    float* out = (float*)d_out;

    // expected layout: out[N] | alpha1[ETOT*4] | alpha2[ETOT]
    size_t need = (size_t)N_NODES + (size_t)ETOT * (HEADS + 1);
    float *a1, *a2;
    if ((size_t)out_size >= need) {
        a1 = out + N_NODES;
        a2 = a1 + (size_t)ETOT * HEADS;
    } else {
        void* p;
        cudaGetSymbolAddress(&p, g_a1_fb); a1 = (float*)p;
        cudaGetSymbolAddress(&p, g_a2_fb); a2 = (float*)p;
    }

    auto cdiv = [](long a, long b) { return (int)((a + b - 1) / b); };

    float *ph1, *px2, *ph2, *ps1, *pd1, *ps2, *pd2;
    { void* p;
      cudaGetSymbolAddress(&p, g_h1); ph1 = (float*)p;
      cudaGetSymbolAddress(&p, g_x2); px2 = (float*)p;
      cudaGetSymbolAddress(&p, g_h2); ph2 = (float*)p;
      cudaGetSymbolAddress(&p, g_s1); ps1 = (float*)p;
      cudaGetSymbolAddress(&p, g_d1); pd1 = (float*)p;
      cudaGetSymbolAddress(&p, g_s2); ps2 = (float*)p;
      cudaGetSymbolAddress(&p, g_d2); pd2 = (float*)p;
    }

    // side stream for the CSR build (fork-join; both branches rejoin before agg1)
    cudaStream_t side;
    cudaStreamCreateWithFlags(&side, cudaStreamNonBlocking);
    cudaEvent_t evF, evJ;
    cudaEventCreateWithFlags(&evF, cudaEventDisableTiming);
    cudaEventCreateWithFlags(&evJ, cudaEventDisableTiming);

    cudaEventRecord(evF, 0);
    cudaStreamWaitEvent(side, evF, 0);

    // ---- CSR build on side stream (independent of GEMM1) ----
    zero_cnt_kernel<<<cdiv(N_PAD / 4, 256), 256, 0, side>>>();
    hist_kernel<<<cdiv(cdiv(ETOT, 4), 256), 256, 0, side>>>(ei);
    scan_kernel<<<1, SCAN_T, 0, side>>>();
    scatter_kernel<<<cdiv(cdiv(ETOT, 4), 256), 256, 0, side>>>(ei);
    cudaEventRecord(evJ, side);

    // ---- layer 1 GEMM + fused logits on main stream (concurrent with CSR) ----
    gemm_sd1_kernel<<<cdiv(N_NODES, 16), 256>>>(x, W1, ph1, as1, ad1, ps1, pd1, N_NODES);

    cudaStreamWaitEvent(0, evJ, 0);     // join: agg1 needs CSR + h1 + s1/d1
    agg1_kernel<<<cdiv((long)N_NODES * 32, 256), 256>>>(a1, b1, ln1g, ln1b);

    // ---- layer 2 ----
    gemm_sd2_kernel<<<cdiv(N_NODES, 32), 128>>>(px2, W2, ph2, as2, ad2, ps2, pd2, N_NODES);
    agg2_kernel<<<cdiv(N_NODES, 8), 256>>>(a2, b2, ln2g, ln2b, hW1, hb1, hW2, hb2, out);
}

// round 8
// speedup vs baseline: 1.9407x; 1.0323x over previous
#include <cuda_runtime.h>
#include <cuda_fp16.h>
#include <math.h>

#define N_NODES 50000
#define E_EDGES 800000
#define ETOT    (E_EDGES + N_NODES)   // 850000
#define F_IN    128
#define HID     64
#define HEADS   4
#define C1      (HEADS * HID)         // 256
#define SLOPE   0.2f
#define EPS_SM  1e-16f

#define SCAN_T  1024
#define SCAN_CH 52                     // 52*1024 = 53248 >= N_NODES, /4
#define N_PAD   (SCAN_T * SCAN_CH)

// ------------------------- device scratch (no allocs allowed) ---------------
__device__ __half g_h1h[(size_t)N_NODES * C1];    // x @ W1 (fp16 storage)
__device__ float  g_x2 [(size_t)N_NODES * C1];    // layer1 output after LN/ELU (fp32)
__device__ __half g_h2h[(size_t)N_NODES * HID];   // x2 @ W2 (fp16 storage)
__device__ float g_s1  [N_NODES * HEADS];
__device__ float g_d1  [N_NODES * HEADS];
__device__ float g_s2  [N_NODES];
__device__ float g_d2  [N_NODES];
// CSR by destination (rebuilt every launch; deterministic work)
__device__ __align__(16) int g_cnt   [N_PAD];
__device__ __align__(16) int g_rowptr[N_PAD + 4];
__device__ __align__(16) int g_wofs  [N_PAD + 4];
__device__ int2 g_epack[ETOT];                    // {src, eid} per CSR slot
// fallback alpha scratch in case d_out layout differs from expectation
__device__ float g_a1_fb[(size_t)ETOT * HEADS];
__device__ float g_a2_fb[(size_t)ETOT];

// ------------------------- helpers ------------------------------------------
__device__ __forceinline__ float lrelu(float v) { return v > 0.f ? v : SLOPE * v; }
__device__ __forceinline__ float eluf(float v)  { return v > 0.f ? v : expm1f(v); }

__device__ __forceinline__ float wredsum(float v) {
#pragma unroll
    for (int o = 16; o > 0; o >>= 1) v += __shfl_xor_sync(0xffffffffu, v, o);
    return v;
}

// ------------------------- CSR build -----------------------------------------
__global__ void zero_cnt_kernel() {
    int i = blockIdx.x * blockDim.x + threadIdx.x;
    if (i < N_PAD / 4) *reinterpret_cast<int4*>(&g_cnt[i * 4]) = make_int4(0, 0, 0, 0);
}

__global__ void hist_kernel(const int* __restrict__ ei) {
    int i0 = (blockIdx.x * blockDim.x + threadIdx.x) * 4;
    if (i0 >= ETOT) return;
    if (i0 + 4 <= E_EDGES) {
        int4 d = *reinterpret_cast<const int4*>(&ei[E_EDGES + i0]);
        atomicAdd(&g_cnt[d.x], 1);
        atomicAdd(&g_cnt[d.y], 1);
        atomicAdd(&g_cnt[d.z], 1);
        atomicAdd(&g_cnt[d.w], 1);
    } else {
#pragma unroll
        for (int t = 0; t < 4; t++) {
            int e = i0 + t;
            if (e < ETOT) {
                int dst = (e < E_EDGES) ? ei[E_EDGES + e] : e - E_EDGES;
                atomicAdd(&g_cnt[dst], 1);
            }
        }
    }
}

__global__ __launch_bounds__(SCAN_T) void scan_kernel() {
    __shared__ int sums[SCAN_T];
    int t = threadIdx.x;
    int lo = t * SCAN_CH;
    const int4* cp = reinterpret_cast<const int4*>(&g_cnt[lo]);
    int local = 0;
#pragma unroll
    for (int i = 0; i < SCAN_CH / 4; i++) {
        int4 c = cp[i];
        local += c.x + c.y + c.z + c.w;
    }
    sums[t] = local;
    __syncthreads();
    for (int off = 1; off < SCAN_T; off <<= 1) {
        int v = (t >= off) ? sums[t - off] : 0;
        __syncthreads();
        sums[t] += v;
        __syncthreads();
    }
    int run = sums[t] - local;                    // exclusive prefix
    int4* rp = reinterpret_cast<int4*>(&g_rowptr[lo]);
    int4* wp = reinterpret_cast<int4*>(&g_wofs[lo]);
#pragma unroll
    for (int i = 0; i < SCAN_CH / 4; i++) {
        int4 c = cp[i];
        int4 o;
        o.x = run; run += c.x;
        o.y = run; run += c.y;
        o.z = run; run += c.z;
        o.w = run; run += c.w;
        rp[i] = o; wp[i] = o;
    }
}

__global__ void scatter_kernel(const int* __restrict__ ei) {
    int i0 = (blockIdx.x * blockDim.x + threadIdx.x) * 4;
    if (i0 >= ETOT) return;
    if (i0 + 4 <= E_EDGES) {
        int4 s = *reinterpret_cast<const int4*>(&ei[i0]);
        int4 d = *reinterpret_cast<const int4*>(&ei[E_EDGES + i0]);
        int sl;
        sl = atomicAdd(&g_wofs[d.x], 1); g_epack[sl] = make_int2(s.x, i0);
        sl = atomicAdd(&g_wofs[d.y], 1); g_epack[sl] = make_int2(s.y, i0 + 1);
        sl = atomicAdd(&g_wofs[d.z], 1); g_epack[sl] = make_int2(s.z, i0 + 2);
        sl = atomicAdd(&g_wofs[d.w], 1); g_epack[sl] = make_int2(s.w, i0 + 3);
    } else {
#pragma unroll
        for (int t = 0; t < 4; t++) {
            int e = i0 + t;
            if (e < ETOT) {
                int src, dst;
                if (e < E_EDGES) { src = ei[e]; dst = ei[E_EDGES + e]; }
                else             { src = dst = e - E_EDGES; }
                int slot = atomicAdd(&g_wofs[dst], 1);
                g_epack[slot] = make_int2(src, e);
            }
        }
    }
}

// ---- layer-1 GEMM + fused logits; Y stored fp16 -----------------------------
// Y = X[.,128] @ W1[128,256]; S/D[gr,h] via 16-lane shuffle reduce.
__global__ __launch_bounds__(256)
void gemm_sd1_kernel(const float* __restrict__ X, const float* __restrict__ W,
                     __half* __restrict__ Yh,
                     const float* __restrict__ asrc, const float* __restrict__ adst,
                     float* __restrict__ S, float* __restrict__ D, int nrows) {
    constexpr int K = 128, NCOLS = 256, TM = 16, NT = 256;
    __shared__ float xs[TM * K];

    int tid     = threadIdx.x;
    int rowbase = blockIdx.x * TM;
    for (int i = tid; i < TM * K; i += NT) {
        int r = i / K, c = i - r * K;
        int gr = rowbase + r;
        xs[i] = (gr < nrows) ? X[(size_t)gr * K + c] : 0.f;
    }
    __syncthreads();

    int tx = tid % 64, ty = tid / 64;
    int c0 = tx * 4;
    float acc[4][4];
#pragma unroll
    for (int i = 0; i < 4; i++)
#pragma unroll
        for (int j = 0; j < 4; j++) acc[i][j] = 0.f;

#pragma unroll 4
    for (int k = 0; k < K; k++) {
        float4 w = *reinterpret_cast<const float4*>(&W[(size_t)k * NCOLS + c0]);
#pragma unroll
        for (int i = 0; i < 4; i++) {
            float a = xs[(ty * 4 + i) * K + k];
            acc[i][0] += a * w.x; acc[i][1] += a * w.y;
            acc[i][2] += a * w.z; acc[i][3] += a * w.w;
        }
    }

    float4 av = *reinterpret_cast<const float4*>(&asrc[c0]);
    float4 dv = *reinterpret_cast<const float4*>(&adst[c0]);
    int lane = tid & 31;
    int h0   = 2 * ((tid >> 5) & 1);    // warp covers heads h0, h0+1

#pragma unroll
    for (int i = 0; i < 4; i++) {
        int gr = rowbase + ty * 4 + i;
        if (gr < nrows) {
            __half2 p0 = __floats2half2_rn(acc[i][0], acc[i][1]);
            __half2 p1 = __floats2half2_rn(acc[i][2], acc[i][3]);
            uint2 st = make_uint2(*reinterpret_cast<unsigned*>(&p0),
                                  *reinterpret_cast<unsigned*>(&p1));
            *reinterpret_cast<uint2*>(&Yh[(size_t)gr * NCOLS + c0]) = st;
        }
        float ps = acc[i][0] * av.x + acc[i][1] * av.y + acc[i][2] * av.z + acc[i][3] * av.w;
        float pd = acc[i][0] * dv.x + acc[i][1] * dv.y + acc[i][2] * dv.z + acc[i][3] * dv.w;
#pragma unroll
        for (int o = 8; o > 0; o >>= 1) {
            ps += __shfl_xor_sync(0xffffffffu, ps, o);
            pd += __shfl_xor_sync(0xffffffffu, pd, o);
        }
        if (gr < nrows) {
            if (lane == 0)  { S[gr * 4 + h0]     = ps; D[gr * 4 + h0]     = pd; }
            if (lane == 16) { S[gr * 4 + h0 + 1] = ps; D[gr * 4 + h0 + 1] = pd; }
        }
    }
}

// ---- layer-2 GEMM + fused logits; Y stored fp16 -----------------------------
__global__ __launch_bounds__(128)
void gemm_sd2_kernel(const float* __restrict__ X, const float* __restrict__ W,
                     __half* __restrict__ Yh,
                     const float* __restrict__ asrc, const float* __restrict__ adst,
                     float* __restrict__ S, float* __restrict__ D, int nrows) {
    constexpr int K = 256, NCOLS = 64, TM = 32, NT = 128;
    __shared__ float xs[TM * K];

    int tid     = threadIdx.x;
    int rowbase = blockIdx.x * TM;
    for (int i = tid; i < TM * K; i += NT) {
        int r = i / K, c = i - r * K;
        int gr = rowbase + r;
        xs[i] = (gr < nrows) ? X[(size_t)gr * K + c] : 0.f;
    }
    __syncthreads();

    int tx = tid % 16, ty = tid / 16;
    int c0 = tx * 4;
    float acc[4][4];
#pragma unroll
    for (int i = 0; i < 4; i++)
#pragma unroll
        for (int j = 0; j < 4; j++) acc[i][j] = 0.f;

#pragma unroll 4
    for (int k = 0; k < K; k++) {
        float4 w = *reinterpret_cast<const float4*>(&W[(size_t)k * NCOLS + c0]);
#pragma unroll
        for (int i = 0; i < 4; i++) {
            float a = xs[(ty * 4 + i) * K + k];
            acc[i][0] += a * w.x; acc[i][1] += a * w.y;
            acc[i][2] += a * w.z; acc[i][3] += a * w.w;
        }
    }

    float4 av = *reinterpret_cast<const float4*>(&asrc[c0]);
    float4 dv = *reinterpret_cast<const float4*>(&adst[c0]);
    int lane = tid & 31;

#pragma unroll
    for (int i = 0; i < 4; i++) {
        int gr = rowbase + ty * 4 + i;
        if (gr < nrows) {
            __half2 p0 = __floats2half2_rn(acc[i][0], acc[i][1]);
            __half2 p1 = __floats2half2_rn(acc[i][2], acc[i][3]);
            uint2 st = make_uint2(*reinterpret_cast<unsigned*>(&p0),
                                  *reinterpret_cast<unsigned*>(&p1));
            *reinterpret_cast<uint2*>(&Yh[(size_t)gr * NCOLS + c0]) = st;
        }
        float ps = acc[i][0] * av.x + acc[i][1] * av.y + acc[i][2] * av.z + acc[i][3] * av.w;
        float pd = acc[i][0] * dv.x + acc[i][1] * dv.y + acc[i][2] * dv.z + acc[i][3] * dv.w;
#pragma unroll
        for (int o = 8; o > 0; o >>= 1) {
            ps += __shfl_xor_sync(0xffffffffu, ps, o);
            pd += __shfl_xor_sync(0xffffffffu, pd, o);
        }
        if (gr < nrows && (lane == 0 || lane == 16)) { S[gr] = ps; D[gr] = pd; }
    }
}

// ------------------------- layer 1: single-pass gather + LN + ELU ------------
// one warp per node; lane's 8-feature slice = ONE uint4 (8 fp16) per edge
__global__ __launch_bounds__(256)
void agg1_kernel(float* __restrict__ a1, const float* __restrict__ b1,
                 const float* __restrict__ gam, const float* __restrict__ bet) {
    int n    = (blockIdx.x * blockDim.x + threadIdx.x) >> 5;
    int lane = threadIdx.x & 31;
    if (n >= N_NODES) return;
    int base = g_rowptr[n], end = g_rowptr[n + 1];
    float4 d = *reinterpret_cast<const float4*>(&g_d1[n * 4]);

    int h  = lane >> 3;           // head for this lane's 8-feature slice
    int c0 = lane * 8;
    float acc[8];
#pragma unroll
    for (int i = 0; i < 8; i++) acc[i] = 0.f;
    float4 den = make_float4(0.f, 0.f, 0.f, 0.f);

    int j = base;
    for (; j + 1 < end; j += 2) {
        int2 p0 = g_epack[j], p1 = g_epack[j + 1];
        int src0 = p0.x, src1 = p1.x;
        float4 s0 = *reinterpret_cast<const float4*>(&g_s1[src0 * 4]);
        float4 s1 = *reinterpret_cast<const float4*>(&g_s1[src1 * 4]);
        uint4 hv0 = *reinterpret_cast<const uint4*>(&g_h1h[(size_t)src0 * C1 + c0]);
        uint4 hv1 = *reinterpret_cast<const uint4*>(&g_h1h[(size_t)src1 * C1 + c0]);
        float4 e0, e1;
        e0.x = __expf(lrelu(s0.x + d.x)); e0.y = __expf(lrelu(s0.y + d.y));
        e0.z = __expf(lrelu(s0.z + d.z)); e0.w = __expf(lrelu(s0.w + d.w));
        e1.x = __expf(lrelu(s1.x + d.x)); e1.y = __expf(lrelu(s1.y + d.y));
        e1.z = __expf(lrelu(s1.z + d.z)); e1.w = __expf(lrelu(s1.w + d.w));
        den.x += e0.x + e1.x; den.y += e0.y + e1.y;
        den.z += e0.z + e1.z; den.w += e0.w + e1.w;
        float a0 = (h == 0) ? e0.x : (h == 1) ? e0.y : (h == 2) ? e0.z : e0.w;
        float a1w = (h == 0) ? e1.x : (h == 1) ? e1.y : (h == 2) ? e1.z : e1.w;
        float2 f00 = __half22float2(*reinterpret_cast<__half2*>(&hv0.x));
        float2 f01 = __half22float2(*reinterpret_cast<__half2*>(&hv0.y));
        float2 f02 = __half22float2(*reinterpret_cast<__half2*>(&hv0.z));
        float2 f03 = __half22float2(*reinterpret_cast<__half2*>(&hv0.w));
        float2 f10 = __half22float2(*reinterpret_cast<__half2*>(&hv1.x));
        float2 f11 = __half22float2(*reinterpret_cast<__half2*>(&hv1.y));
        float2 f12 = __half22float2(*reinterpret_cast<__half2*>(&hv1.z));
        float2 f13 = __half22float2(*reinterpret_cast<__half2*>(&hv1.w));
        acc[0] += f00.x * a0 + f10.x * a1w; acc[1] += f00.y * a0 + f10.y * a1w;
        acc[2] += f01.x * a0 + f11.x * a1w; acc[3] += f01.y * a0 + f11.y * a1w;
        acc[4] += f02.x * a0 + f12.x * a1w; acc[5] += f02.y * a0 + f12.y * a1w;
        acc[6] += f03.x * a0 + f13.x * a1w; acc[7] += f03.y * a0 + f13.y * a1w;
    }
    if (j < end) {
        int2 p = g_epack[j];
        int src = p.x;
        float4 s = *reinterpret_cast<const float4*>(&g_s1[src * 4]);
        float4 e;
        e.x = __expf(lrelu(s.x + d.x)); e.y = __expf(lrelu(s.y + d.y));
        e.z = __expf(lrelu(s.z + d.z)); e.w = __expf(lrelu(s.w + d.w));
        den.x += e.x; den.y += e.y; den.z += e.z; den.w += e.w;
        float a = (h == 0) ? e.x : (h == 1) ? e.y : (h == 2) ? e.z : e.w;
        uint4 hv = *reinterpret_cast<const uint4*>(&g_h1h[(size_t)src * C1 + c0]);
        float2 f0 = __half22float2(*reinterpret_cast<__half2*>(&hv.x));
        float2 f1 = __half22float2(*reinterpret_cast<__half2*>(&hv.y));
        float2 f2 = __half22float2(*reinterpret_cast<__half2*>(&hv.z));
        float2 f3 = __half22float2(*reinterpret_cast<__half2*>(&hv.w));
        acc[0] += f0.x * a; acc[1] += f0.y * a;
        acc[2] += f1.x * a; acc[3] += f1.y * a;
        acc[4] += f2.x * a; acc[5] += f2.y * a;
        acc[6] += f3.x * a; acc[7] += f3.y * a;
    }

    float4 inv = make_float4(1.f / (den.x + EPS_SM), 1.f / (den.y + EPS_SM),
                             1.f / (den.z + EPS_SM), 1.f / (den.w + EPS_SM));

    // alpha writes, lane-parallel
    for (int jj = base + lane; jj < end; jj += 32) {
        int2 p = g_epack[jj];
        float4 s = *reinterpret_cast<const float4*>(&g_s1[p.x * 4]);
        float4 al;
        al.x = __expf(lrelu(s.x + d.x)) * inv.x;
        al.y = __expf(lrelu(s.y + d.y)) * inv.y;
        al.z = __expf(lrelu(s.z + d.z)) * inv.z;
        al.w = __expf(lrelu(s.w + d.w)) * inv.w;
        *reinterpret_cast<float4*>(&a1[(size_t)p.y * 4]) = al;
    }

    float invh = (h == 0) ? inv.x : (h == 1) ? inv.y : (h == 2) ? inv.z : inv.w;
#pragma unroll
    for (int i = 0; i < 8; i++) acc[i] *= invh;

    // epilogue: +b1, LayerNorm(256), ELU -> g_x2
    float4 ba = *reinterpret_cast<const float4*>(&b1[c0]);
    float4 bb = *reinterpret_cast<const float4*>(&b1[c0 + 4]);
    acc[0] += ba.x; acc[1] += ba.y; acc[2] += ba.z; acc[3] += ba.w;
    acc[4] += bb.x; acc[5] += bb.y; acc[6] += bb.z; acc[7] += bb.w;
    float sum = 0.f, sq = 0.f;
#pragma unroll
    for (int i = 0; i < 8; i++) { sum += acc[i]; sq += acc[i] * acc[i]; }
    sum = wredsum(sum); sq = wredsum(sq);
    float mu  = sum * (1.f / 256.f);
    float var = sq * (1.f / 256.f) - mu * mu;
    float rs  = rsqrtf(var + 1e-5f);
    float4 ga = *reinterpret_cast<const float4*>(&gam[c0]);
    float4 gb = *reinterpret_cast<const float4*>(&gam[c0 + 4]);
    float4 ea = *reinterpret_cast<const float4*>(&bet[c0]);
    float4 eb = *reinterpret_cast<const float4*>(&bet[c0 + 4]);
    float4 y0, y1;
    y0.x = eluf((acc[0] - mu) * rs * ga.x + ea.x);
    y0.y = eluf((acc[1] - mu) * rs * ga.y + ea.y);
    y0.z = eluf((acc[2] - mu) * rs * ga.z + ea.z);
    y0.w = eluf((acc[3] - mu) * rs * ga.w + ea.w);
    y1.x = eluf((acc[4] - mu) * rs * gb.x + eb.x);
    y1.y = eluf((acc[5] - mu) * rs * gb.y + eb.y);
    y1.z = eluf((acc[6] - mu) * rs * gb.z + eb.z);
    y1.w = eluf((acc[7] - mu) * rs * gb.w + eb.w);
    float4* orow = reinterpret_cast<float4*>(&g_x2[(size_t)n * C1 + c0]);
    orow[0] = y0; orow[1] = y1;
}

// ------------------------- layer 2: single-pass gather + LN + ELU + head -----
__global__ __launch_bounds__(256)
void agg2_kernel(float* __restrict__ a2, const float* __restrict__ b2,
                 const float* __restrict__ g2, const float* __restrict__ e2,
                 const float* __restrict__ hW1, const float* __restrict__ hb1,
                 const float* __restrict__ hW2, const float* __restrict__ hb2,
                 float* __restrict__ out) {
    __shared__ float w1s[64 * 32];
    __shared__ float w2s[32];
    __shared__ float b1s[32];
    __shared__ float zs[8][64];
    int tid = threadIdx.x;
    for (int i = tid; i < 64 * 32; i += 256) w1s[i] = hW1[i];
    if (tid < 32) { w2s[tid] = hW2[tid]; b1s[tid] = hb1[tid]; }
    __syncthreads();

    int w    = tid >> 5;
    int lane = tid & 31;
    int n = blockIdx.x * 8 + w;
    if (n >= N_NODES) return;

    int base = g_rowptr[n], end = g_rowptr[n + 1];
    float dd = g_d2[n];

    float a0 = 0.f, a1v = 0.f, den = 0.f;
    int c0 = lane * 2;
    int j = base;
    for (; j + 1 < end; j += 2) {
        int2 p0 = g_epack[j], p1 = g_epack[j + 1];
        float e0 = __expf(lrelu(g_s2[p0.x] + dd));
        float e1 = __expf(lrelu(g_s2[p1.x] + dd));
        unsigned u0 = *reinterpret_cast<const unsigned*>(&g_h2h[(size_t)p0.x * HID + c0]);
        unsigned u1 = *reinterpret_cast<const unsigned*>(&g_h2h[(size_t)p1.x * HID + c0]);
        float2 v0 = __half22float2(*reinterpret_cast<__half2*>(&u0));
        float2 v1 = __half22float2(*reinterpret_cast<__half2*>(&u1));
        den += e0 + e1;
        a0  += v0.x * e0 + v1.x * e1;
        a1v += v0.y * e0 + v1.y * e1;
    }
    if (j < end) {
        int2 p = g_epack[j];
        float e = __expf(lrelu(g_s2[p.x] + dd));
        unsigned u = *reinterpret_cast<const unsigned*>(&g_h2h[(size_t)p.x * HID + c0]);
        float2 v = __half22float2(*reinterpret_cast<__half2*>(&u));
        den += e; a0 += v.x * e; a1v += v.y * e;
    }
    float inv = 1.f / (den + EPS_SM);

    for (int jj = base + lane; jj < end; jj += 32) {
        int2 p = g_epack[jj];
        a2[p.y] = __expf(lrelu(g_s2[p.x] + dd)) * inv;
    }
    a0 *= inv; a1v *= inv;

    // +b2, LN(64), ELU
    a0  += b2[c0];
    a1v += b2[c0 + 1];
    float sum = wredsum(a0 + a1v);
    float sq  = wredsum(a0 * a0 + a1v * a1v);
    float mu  = sum * (1.f / 64.f);
    float var = sq * (1.f / 64.f) - mu * mu;
    float rs  = rsqrtf(var + 1e-5f);
    float y0 = eluf((a0  - mu) * rs * g2[c0]     + e2[c0]);
    float y1 = eluf((a1v - mu) * rs * g2[c0 + 1] + e2[c0 + 1]);
    zs[w][c0] = y0; zs[w][c0 + 1] = y1;
    __syncwarp();

    // MLP head: 64 -> 32 -> ReLU -> 1
    float acc = b1s[lane];
#pragma unroll
    for (int k = 0; k < 64; k++) acc += zs[w][k] * w1s[k * 32 + lane];
    acc = fmaxf(acc, 0.f);
    float p = wredsum(acc * w2s[lane]);
    if (lane == 0) out[n] = p + hb2[0];
}

// ------------------------- host launcher -------------------------------------
extern "C" void kernel_launch(void* const* d_in, const int* in_sizes, int n_in,
                              void* d_out, int out_size) {
    const float* x     = (const float*)d_in[0];
    const int*   ei    = (const int*)  d_in[1];
    const float* W1    = (const float*)d_in[2];
    const float* as1   = (const float*)d_in[3];
    const float* ad1   = (const float*)d_in[4];
    const float* b1    = (const float*)d_in[5];
    const float* W2    = (const float*)d_in[6];
    const float* as2   = (const float*)d_in[7];
    const float* ad2   = (const float*)d_in[8];
    const float* b2    = (const float*)d_in[9];
    const float* ln1g  = (const float*)d_in[10];
    const float* ln1b  = (const float*)d_in[11];
    const float* ln2g  = (const float*)d_in[12];
    const float* ln2b  = (const float*)d_in[13];
    const float* hW1   = (const float*)d_in[14];
    const float* hb1   = (const float*)d_in[15];
    const float* hW2   = (const float*)d_in[16];
    const float* hb2   = (const float*)d_in[17];
    float* out = (float*)d_out;

    // expected layout: out[N] | alpha1[ETOT*4] | alpha2[ETOT]
    size_t need = (size_t)N_NODES + (size_t)ETOT * (HEADS + 1);
    float *a1, *a2;
    if ((size_t)out_size >= need) {
        a1 = out + N_NODES;
        a2 = a1 + (size_t)ETOT * HEADS;
    } else {
        void* p;
        cudaGetSymbolAddress(&p, g_a1_fb); a1 = (float*)p;
        cudaGetSymbolAddress(&p, g_a2_fb); a2 = (float*)p;
    }

    auto cdiv = [](long a, long b) { return (int)((a + b - 1) / b); };

    __half *ph1, *ph2;
    float *px2, *ps1, *pd1, *ps2, *pd2;
    { void* p;
      cudaGetSymbolAddress(&p, g_h1h); ph1 = (__half*)p;
      cudaGetSymbolAddress(&p, g_x2);  px2 = (float*)p;
      cudaGetSymbolAddress(&p, g_h2h); ph2 = (__half*)p;
      cudaGetSymbolAddress(&p, g_s1);  ps1 = (float*)p;
      cudaGetSymbolAddress(&p, g_d1);  pd1 = (float*)p;
      cudaGetSymbolAddress(&p, g_s2);  ps2 = (float*)p;
      cudaGetSymbolAddress(&p, g_d2);  pd2 = (float*)p;
    }

    // side stream for the CSR build (fork-join; both branches rejoin before agg1)
    cudaStream_t side;
    cudaStreamCreateWithFlags(&side, cudaStreamNonBlocking);
    cudaEvent_t evF, evJ;
    cudaEventCreateWithFlags(&evF, cudaEventDisableTiming);
    cudaEventCreateWithFlags(&evJ, cudaEventDisableTiming);

    cudaEventRecord(evF, 0);
    cudaStreamWaitEvent(side, evF, 0);

    // ---- CSR build on side stream (independent of GEMM1) ----
    zero_cnt_kernel<<<cdiv(N_PAD / 4, 256), 256, 0, side>>>();
    hist_kernel<<<cdiv(cdiv(ETOT, 4), 256), 256, 0, side>>>(ei);
    scan_kernel<<<1, SCAN_T, 0, side>>>();
    scatter_kernel<<<cdiv(cdiv(ETOT, 4), 256), 256, 0, side>>>(ei);
    cudaEventRecord(evJ, side);

    // ---- layer 1 GEMM + fused logits on main stream (concurrent with CSR) ----
    gemm_sd1_kernel<<<cdiv(N_NODES, 16), 256>>>(x, W1, ph1, as1, ad1, ps1, pd1, N_NODES);

    cudaStreamWaitEvent(0, evJ, 0);     // join: agg1 needs CSR + h1 + s1/d1
    agg1_kernel<<<cdiv((long)N_NODES * 32, 256), 256>>>(a1, b1, ln1g, ln1b);

    // ---- layer 2 ----
    gemm_sd2_kernel<<<cdiv(N_NODES, 32), 128>>>(px2, W2, ph2, as2, ad2, ps2, pd2, N_NODES);
    agg2_kernel<<<cdiv(N_NODES, 8), 256>>>(a2, b2, ln2g, ln2b, hW1, hb1, hW2, hb2, out);
}

// round 9
// speedup vs baseline: 2.4394x; 1.2570x over previous
#include <cuda_runtime.h>
#include <cuda_fp16.h>
#include <mma.h>
#include <math.h>

using namespace nvcuda;

#define N_NODES 50000
#define E_EDGES 800000
#define ETOT    (E_EDGES + N_NODES)   // 850000
#define F_IN    128
#define HID     64
#define HEADS   4
#define C1      (HEADS * HID)         // 256
#define SLOPE   0.2f
#define EPS_SM  1e-16f

#define SCAN_T  1024
#define SCAN_CH 52                     // 52*1024 = 53248 >= N_NODES, /4
#define N_PAD   (SCAN_T * SCAN_CH)

// wmma gemm1 tiling
#define G1_BM    64
#define G1_ALD   136                   // padded half stride for A tile
#define G1_WLD   264                   // padded half stride for W tile
#define G1_SLD   264                   // padded float stride for stage
#define G1_SMEM  ((G1_BM * G1_ALD + 128 * G1_WLD) * 2 > G1_BM * G1_SLD * 4 ? \
                  (G1_BM * G1_ALD + 128 * G1_WLD) * 2 : G1_BM * G1_SLD * 4)

// ------------------------- device scratch (no allocs allowed) ---------------
__device__ __half g_h1h[(size_t)N_NODES * C1];    // x @ W1 (fp16 storage)
__device__ float  g_x2 [(size_t)N_NODES * C1];    // layer1 output after LN/ELU (fp32)
__device__ __half g_h2h[(size_t)N_NODES * HID];   // x2 @ W2 (fp16 storage)
__device__ __half g_w1h[F_IN * C1];               // W1 pre-converted to fp16
__device__ float g_s1  [N_NODES * HEADS];
__device__ float g_d1  [N_NODES * HEADS];
__device__ float g_s2  [N_NODES];
__device__ float g_d2  [N_NODES];
// CSR by destination (rebuilt every launch; deterministic work)
__device__ __align__(16) int g_cnt   [N_PAD];
__device__ __align__(16) int g_rowptr[N_PAD + 4];
__device__ __align__(16) int g_wofs  [N_PAD + 4];
__device__ int2 g_epack[ETOT];                    // {src, eid} per CSR slot
// fallback alpha scratch in case d_out layout differs from expectation
__device__ float g_a1_fb[(size_t)ETOT * HEADS];
__device__ float g_a2_fb[(size_t)ETOT];

// ------------------------- helpers ------------------------------------------
__device__ __forceinline__ float lrelu(float v) { return v > 0.f ? v : SLOPE * v; }
__device__ __forceinline__ float eluf(float v)  { return v > 0.f ? v : expm1f(v); }

__device__ __forceinline__ float wredsum(float v) {
#pragma unroll
    for (int o = 16; o > 0; o >>= 1) v += __shfl_xor_sync(0xffffffffu, v, o);
    return v;
}

__device__ __forceinline__ uint2 pack_half4(float4 v) {
    __half2 h0 = __floats2half2_rn(v.x, v.y);
    __half2 h1 = __floats2half2_rn(v.z, v.w);
    return make_uint2(*reinterpret_cast<unsigned*>(&h0),
                      *reinterpret_cast<unsigned*>(&h1));
}

// ------------------------- CSR build -----------------------------------------
__global__ void zero_cnt_kernel() {
    int i = blockIdx.x * blockDim.x + threadIdx.x;
    if (i < N_PAD / 4) *reinterpret_cast<int4*>(&g_cnt[i * 4]) = make_int4(0, 0, 0, 0);
}

__global__ void hist_kernel(const int* __restrict__ ei) {
    int i0 = (blockIdx.x * blockDim.x + threadIdx.x) * 4;
    if (i0 >= ETOT) return;
    if (i0 + 4 <= E_EDGES) {
        int4 d = *reinterpret_cast<const int4*>(&ei[E_EDGES + i0]);
        atomicAdd(&g_cnt[d.x], 1);
        atomicAdd(&g_cnt[d.y], 1);
        atomicAdd(&g_cnt[d.z], 1);
        atomicAdd(&g_cnt[d.w], 1);
    } else {
#pragma unroll
        for (int t = 0; t < 4; t++) {
            int e = i0 + t;
            if (e < ETOT) {
                int dst = (e < E_EDGES) ? ei[E_EDGES + e] : e - E_EDGES;
                atomicAdd(&g_cnt[dst], 1);
            }
        }
    }
}

__global__ __launch_bounds__(SCAN_T) void scan_kernel() {
    __shared__ int sums[SCAN_T];
    int t = threadIdx.x;
    int lo = t * SCAN_CH;
    const int4* cp = reinterpret_cast<const int4*>(&g_cnt[lo]);
    int local = 0;
#pragma unroll
    for (int i = 0; i < SCAN_CH / 4; i++) {
        int4 c = cp[i];
        local += c.x + c.y + c.z + c.w;
    }
    sums[t] = local;
    __syncthreads();
    for (int off = 1; off < SCAN_T; off <<= 1) {
        int v = (t >= off) ? sums[t - off] : 0;
        __syncthreads();
        sums[t] += v;
        __syncthreads();
    }
    int run = sums[t] - local;                    // exclusive prefix
    int4* rp = reinterpret_cast<int4*>(&g_rowptr[lo]);
    int4* wp = reinterpret_cast<int4*>(&g_wofs[lo]);
#pragma unroll
    for (int i = 0; i < SCAN_CH / 4; i++) {
        int4 c = cp[i];
        int4 o;
        o.x = run; run += c.x;
        o.y = run; run += c.y;
        o.z = run; run += c.z;
        o.w = run; run += c.w;
        rp[i] = o; wp[i] = o;
    }
}

__global__ void scatter_kernel(const int* __restrict__ ei) {
    int i0 = (blockIdx.x * blockDim.x + threadIdx.x) * 4;
    if (i0 >= ETOT) return;
    if (i0 + 4 <= E_EDGES) {
        int4 s = *reinterpret_cast<const int4*>(&ei[i0]);
        int4 d = *reinterpret_cast<const int4*>(&ei[E_EDGES + i0]);
        int sl;
        sl = atomicAdd(&g_wofs[d.x], 1); g_epack[sl] = make_int2(s.x, i0);
        sl = atomicAdd(&g_wofs[d.y], 1); g_epack[sl] = make_int2(s.y, i0 + 1);
        sl = atomicAdd(&g_wofs[d.z], 1); g_epack[sl] = make_int2(s.z, i0 + 2);
        sl = atomicAdd(&g_wofs[d.w], 1); g_epack[sl] = make_int2(s.w, i0 + 3);
    } else {
#pragma unroll
        for (int t = 0; t < 4; t++) {
            int e = i0 + t;
            if (e < ETOT) {
                int src, dst;
                if (e < E_EDGES) { src = ei[e]; dst = ei[E_EDGES + e]; }
                else             { src = dst = e - E_EDGES; }
                int slot = atomicAdd(&g_wofs[dst], 1);
                g_epack[slot] = make_int2(src, e);
            }
        }
    }
}

// ------------------------- W1 fp32 -> fp16 (once per launch) -----------------
__global__ void conv_w1_kernel(const float* __restrict__ W) {
    int i4 = (blockIdx.x * blockDim.x + threadIdx.x) * 4;
    if (i4 < F_IN * C1) {
        float4 v = *reinterpret_cast<const float4*>(&W[i4]);
        *reinterpret_cast<uint2*>(&g_w1h[i4]) = pack_half4(v);
    }
}

// ---- layer-1 GEMM on tensor cores (HMMA) + fused logits ---------------------
// block: 64 rows x 256 cols, 8 warps. A fp32->fp16 on load; W1 pre-converted.
// fp32 accumulators staged to smem; epilogue computes s/d per (row, head).
__global__ __launch_bounds__(256)
void gemm1_wmma_kernel(const float* __restrict__ X,
                       const float* __restrict__ asrc, const float* __restrict__ adst,
                       __half* __restrict__ Yh,
                       float* __restrict__ S, float* __restrict__ D, int nrows) {
    extern __shared__ char smraw[];
    __half* Ah  = reinterpret_cast<__half*>(smraw);                      // [64][G1_ALD]
    __half* Wh  = reinterpret_cast<__half*>(smraw) + G1_BM * G1_ALD;     // [128][G1_WLD]
    float*  stg = reinterpret_cast<float*>(smraw);                       // [64][G1_SLD] aliased

    int tid = threadIdx.x;
    int rowbase = blockIdx.x * G1_BM;

    // load A tile (64 x 128 fp32 -> fp16), zero-pad beyond nrows
    for (int i = tid * 4; i < G1_BM * F_IN; i += 256 * 4) {
        int r = i >> 7, c = i & 127;
        int gr = rowbase + r;
        float4 v = (gr < nrows) ? *reinterpret_cast<const float4*>(&X[(size_t)gr * F_IN + c])
                                : make_float4(0.f, 0.f, 0.f, 0.f);
        *reinterpret_cast<uint2*>(&Ah[r * G1_ALD + c]) = pack_half4(v);
    }
    // load W tile (128 x 256 fp16, padded stride)
    for (int i = tid * 8; i < F_IN * C1; i += 256 * 8) {
        int k = i >> 8, c = i & 255;
        uint4 v = *reinterpret_cast<const uint4*>(&g_w1h[i]);
        *reinterpret_cast<uint4*>(&Wh[k * G1_WLD + c]) = v;
    }
    __syncthreads();

    int w = tid >> 5;
    int r0 = (w & 3) * 16;              // 4 row groups of 16
    int cb = (w >> 2) * 128;            // 2 column halves of 128

    wmma::fragment<wmma::accumulator, 16, 16, 16, float> acc[8];
#pragma unroll
    for (int f = 0; f < 8; f++) wmma::fill_fragment(acc[f], 0.f);

#pragma unroll
    for (int kk = 0; kk < F_IN; kk += 16) {
        wmma::fragment<wmma::matrix_a, 16, 16, 16, __half, wmma::row_major> af;
        wmma::load_matrix_sync(af, Ah + r0 * G1_ALD + kk, G1_ALD);
#pragma unroll
        for (int f = 0; f < 8; f++) {
            wmma::fragment<wmma::matrix_b, 16, 16, 16, __half, wmma::row_major> bf;
            wmma::load_matrix_sync(bf, Wh + kk * G1_WLD + cb + f * 16, G1_WLD);
            wmma::mma_sync(acc[f], af, bf, acc[f]);
        }
    }
    __syncthreads();                     // Ah/Wh dead; stage aliases them
#pragma unroll
    for (int f = 0; f < 8; f++)
        wmma::store_matrix_sync(stg + r0 * G1_SLD + cb + f * 16, acc[f],
                                G1_SLD, wmma::mem_row_major);
    __syncthreads();

    // epilogue: thread -> (row, head); 64 cols each
    int r = tid >> 2, q = tid & 3;
    int gr = rowbase + r;
    if (gr < nrows) {
        const float* as = asrc + q * 64;
        const float* ad = adst + q * 64;
        const float* row = stg + r * G1_SLD + q * 64;
        __half* yp = Yh + (size_t)gr * C1 + q * 64;
        float s = 0.f, dd = 0.f;
#pragma unroll
        for (int i = 0; i < 64; i += 4) {
            float4 v = *reinterpret_cast<const float4*>(&row[i]);
            float4 a = *reinterpret_cast<const float4*>(&as[i]);
            float4 b = *reinterpret_cast<const float4*>(&ad[i]);
            s  += v.x * a.x + v.y * a.y + v.z * a.z + v.w * a.w;
            dd += v.x * b.x + v.y * b.y + v.z * b.z + v.w * b.w;
            *reinterpret_cast<uint2*>(&yp[i]) = pack_half4(v);
        }
        S[gr * 4 + q] = s;
        D[gr * 4 + q] = dd;
    }
}

// ---- layer-2 GEMM + fused logits; Y stored fp16 (proven FFMA version) -------
__global__ __launch_bounds__(128)
void gemm_sd2_kernel(const float* __restrict__ X, const float* __restrict__ W,
                     __half* __restrict__ Yh,
                     const float* __restrict__ asrc, const float* __restrict__ adst,
                     float* __restrict__ S, float* __restrict__ D, int nrows) {
    constexpr int K = 256, NCOLS = 64, TM = 32, NT = 128;
    __shared__ float xs[TM * K];

    int tid     = threadIdx.x;
    int rowbase = blockIdx.x * TM;
    for (int i = tid; i < TM * K; i += NT) {
        int r = i / K, c = i - r * K;
        int gr = rowbase + r;
        xs[i] = (gr < nrows) ? X[(size_t)gr * K + c] : 0.f;
    }
    __syncthreads();

    int tx = tid % 16, ty = tid / 16;
    int c0 = tx * 4;
    float acc[4][4];
#pragma unroll
    for (int i = 0; i < 4; i++)
#pragma unroll
        for (int j = 0; j < 4; j++) acc[i][j] = 0.f;

#pragma unroll 4
    for (int k = 0; k < K; k++) {
        float4 w = *reinterpret_cast<const float4*>(&W[(size_t)k * NCOLS + c0]);
#pragma unroll
        for (int i = 0; i < 4; i++) {
            float a = xs[(ty * 4 + i) * K + k];
            acc[i][0] += a * w.x; acc[i][1] += a * w.y;
            acc[i][2] += a * w.z; acc[i][3] += a * w.w;
        }
    }

    float4 av = *reinterpret_cast<const float4*>(&asrc[c0]);
    float4 dv = *reinterpret_cast<const float4*>(&adst[c0]);
    int lane = tid & 31;

#pragma unroll
    for (int i = 0; i < 4; i++) {
        int gr = rowbase + ty * 4 + i;
        if (gr < nrows) {
            *reinterpret_cast<uint2*>(&Yh[(size_t)gr * NCOLS + c0]) =
                pack_half4(make_float4(acc[i][0], acc[i][1], acc[i][2], acc[i][3]));
        }
        float ps = acc[i][0] * av.x + acc[i][1] * av.y + acc[i][2] * av.z + acc[i][3] * av.w;
        float pd = acc[i][0] * dv.x + acc[i][1] * dv.y + acc[i][2] * dv.z + acc[i][3] * dv.w;
#pragma unroll
        for (int o = 8; o > 0; o >>= 1) {
            ps += __shfl_xor_sync(0xffffffffu, ps, o);
            pd += __shfl_xor_sync(0xffffffffu, pd, o);
        }
        if (gr < nrows && (lane == 0 || lane == 16)) { S[gr] = ps; D[gr] = pd; }
    }
}

// ------------------------- layer 1: single-pass gather + LN + ELU ------------
__global__ __launch_bounds__(256)
void agg1_kernel(float* __restrict__ a1, const float* __restrict__ b1,
                 const float* __restrict__ gam, const float* __restrict__ bet) {
    int n    = (blockIdx.x * blockDim.x + threadIdx.x) >> 5;
    int lane = threadIdx.x & 31;
    if (n >= N_NODES) return;
    int base = g_rowptr[n], end = g_rowptr[n + 1];
    float4 d = *reinterpret_cast<const float4*>(&g_d1[n * 4]);

    int h  = lane >> 3;           // head for this lane's 8-feature slice
    int c0 = lane * 8;
    float acc[8];
#pragma unroll
    for (int i = 0; i < 8; i++) acc[i] = 0.f;
    float4 den = make_float4(0.f, 0.f, 0.f, 0.f);

    int j = base;
    for (; j + 1 < end; j += 2) {
        int2 p0 = g_epack[j], p1 = g_epack[j + 1];
        int src0 = p0.x, src1 = p1.x;
        float4 s0 = *reinterpret_cast<const float4*>(&g_s1[src0 * 4]);
        float4 s1 = *reinterpret_cast<const float4*>(&g_s1[src1 * 4]);
        uint4 hv0 = *reinterpret_cast<const uint4*>(&g_h1h[(size_t)src0 * C1 + c0]);
        uint4 hv1 = *reinterpret_cast<const uint4*>(&g_h1h[(size_t)src1 * C1 + c0]);
        float4 e0, e1;
        e0.x = __expf(lrelu(s0.x + d.x)); e0.y = __expf(lrelu(s0.y + d.y));
        e0.z = __expf(lrelu(s0.z + d.z)); e0.w = __expf(lrelu(s0.w + d.w));
        e1.x = __expf(lrelu(s1.x + d.x)); e1.y = __expf(lrelu(s1.y + d.y));
        e1.z = __expf(lrelu(s1.z + d.z)); e1.w = __expf(lrelu(s1.w + d.w));
        den.x += e0.x + e1.x; den.y += e0.y + e1.y;
        den.z += e0.z + e1.z; den.w += e0.w + e1.w;
        float a0 = (h == 0) ? e0.x : (h == 1) ? e0.y : (h == 2) ? e0.z : e0.w;
        float a1w = (h == 0) ? e1.x : (h == 1) ? e1.y : (h == 2) ? e1.z : e1.w;
        float2 f00 = __half22float2(*reinterpret_cast<__half2*>(&hv0.x));
        float2 f01 = __half22float2(*reinterpret_cast<__half2*>(&hv0.y));
        float2 f02 = __half22float2(*reinterpret_cast<__half2*>(&hv0.z));
        float2 f03 = __half22float2(*reinterpret_cast<__half2*>(&hv0.w));
        float2 f10 = __half22float2(*reinterpret_cast<__half2*>(&hv1.x));
        float2 f11 = __half22float2(*reinterpret_cast<__half2*>(&hv1.y));
        float2 f12 = __half22float2(*reinterpret_cast<__half2*>(&hv1.z));
        float2 f13 = __half22float2(*reinterpret_cast<__half2*>(&hv1.w));
        acc[0] += f00.x * a0 + f10.x * a1w; acc[1] += f00.y * a0 + f10.y * a1w;
        acc[2] += f01.x * a0 + f11.x * a1w; acc[3] += f01.y * a0 + f11.y * a1w;
        acc[4] += f02.x * a0 + f12.x * a1w; acc[5] += f02.y * a0 + f12.y * a1w;
        acc[6] += f03.x * a0 + f13.x * a1w; acc[7] += f03.y * a0 + f13.y * a1w;
    }
    if (j < end) {
        int2 p = g_epack[j];
        int src = p.x;
        float4 s = *reinterpret_cast<const float4*>(&g_s1[src * 4]);
        float4 e;
        e.x = __expf(lrelu(s.x + d.x)); e.y = __expf(lrelu(s.y + d.y));
        e.z = __expf(lrelu(s.z + d.z)); e.w = __expf(lrelu(s.w + d.w));
        den.x += e.x; den.y += e.y; den.z += e.z; den.w += e.w;
        float a = (h == 0) ? e.x : (h == 1) ? e.y : (h == 2) ? e.z : e.w;
        uint4 hv = *reinterpret_cast<const uint4*>(&g_h1h[(size_t)src * C1 + c0]);
        float2 f0 = __half22float2(*reinterpret_cast<__half2*>(&hv.x));
        float2 f1 = __half22float2(*reinterpret_cast<__half2*>(&hv.y));
        float2 f2 = __half22float2(*reinterpret_cast<__half2*>(&hv.z));
        float2 f3 = __half22float2(*reinterpret_cast<__half2*>(&hv.w));
        acc[0] += f0.x * a; acc[1] += f0.y * a;
        acc[2] += f1.x * a; acc[3] += f1.y * a;
        acc[4] += f2.x * a; acc[5] += f2.y * a;
        acc[6] += f3.x * a; acc[7] += f3.y * a;
    }

    float4 inv = make_float4(1.f / (den.x + EPS_SM), 1.f / (den.y + EPS_SM),
                             1.f / (den.z + EPS_SM), 1.f / (den.w + EPS_SM));

    // alpha writes, lane-parallel
    for (int jj = base + lane; jj < end; jj += 32) {
        int2 p = g_epack[jj];
        float4 s = *reinterpret_cast<const float4*>(&g_s1[p.x * 4]);
        float4 al;
        al.x = __expf(lrelu(s.x + d.x)) * inv.x;
        al.y = __expf(lrelu(s.y + d.y)) * inv.y;
        al.z = __expf(lrelu(s.z + d.z)) * inv.z;
        al.w = __expf(lrelu(s.w + d.w)) * inv.w;
        *reinterpret_cast<float4*>(&a1[(size_t)p.y * 4]) = al;
    }

    float invh = (h == 0) ? inv.x : (h == 1) ? inv.y : (h == 2) ? inv.z : inv.w;
#pragma unroll
    for (int i = 0; i < 8; i++) acc[i] *= invh;

    // epilogue: +b1, LayerNorm(256), ELU -> g_x2
    float4 ba = *reinterpret_cast<const float4*>(&b1[c0]);
    float4 bb = *reinterpret_cast<const float4*>(&b1[c0 + 4]);
    acc[0] += ba.x; acc[1] += ba.y; acc[2] += ba.z; acc[3] += ba.w;
    acc[4] += bb.x; acc[5] += bb.y; acc[6] += bb.z; acc[7] += bb.w;
    float sum = 0.f, sq = 0.f;
#pragma unroll
    for (int i = 0; i < 8; i++) { sum += acc[i]; sq += acc[i] * acc[i]; }
    sum = wredsum(sum); sq = wredsum(sq);
    float mu  = sum * (1.f / 256.f);
    float var = sq * (1.f / 256.f) - mu * mu;
    float rs  = rsqrtf(var + 1e-5f);
    float4 ga = *reinterpret_cast<const float4*>(&gam[c0]);
    float4 gb = *reinterpret_cast<const float4*>(&gam[c0 + 4]);
    float4 ea = *reinterpret_cast<const float4*>(&bet[c0]);
    float4 eb = *reinterpret_cast<const float4*>(&bet[c0 + 4]);
    float4 y0, y1;
    y0.x = eluf((acc[0] - mu) * rs * ga.x + ea.x);
    y0.y = eluf((acc[1] - mu) * rs * ga.y + ea.y);
    y0.z = eluf((acc[2] - mu) * rs * ga.z + ea.z);
    y0.w = eluf((acc[3] - mu) * rs * ga.w + ea.w);
    y1.x = eluf((acc[4] - mu) * rs * gb.x + eb.x);
    y1.y = eluf((acc[5] - mu) * rs * gb.y + eb.y);
    y1.z = eluf((acc[6] - mu) * rs * gb.z + eb.z);
    y1.w = eluf((acc[7] - mu) * rs * gb.w + eb.w);
    float4* orow = reinterpret_cast<float4*>(&g_x2[(size_t)n * C1 + c0]);
    orow[0] = y0; orow[1] = y1;
}

// ------------------------- layer 2: single-pass gather + LN + ELU + head -----
__global__ __launch_bounds__(256)
void agg2_kernel(float* __restrict__ a2, const float* __restrict__ b2,
                 const float* __restrict__ g2, const float* __restrict__ e2,
                 const float* __restrict__ hW1, const float* __restrict__ hb1,
                 const float* __restrict__ hW2, const float* __restrict__ hb2,
                 float* __restrict__ out) {
    __shared__ float w1s[64 * 32];
    __shared__ float w2s[32];
    __shared__ float b1s[32];
    __shared__ float zs[8][64];
    int tid = threadIdx.x;
    for (int i = tid; i < 64 * 32; i += 256) w1s[i] = hW1[i];
    if (tid < 32) { w2s[tid] = hW2[tid]; b1s[tid] = hb1[tid]; }
    __syncthreads();

    int w    = tid >> 5;
    int lane = tid & 31;
    int n = blockIdx.x * 8 + w;
    if (n >= N_NODES) return;

    int base = g_rowptr[n], end = g_rowptr[n + 1];
    float dd = g_d2[n];

    float a0 = 0.f, a1v = 0.f, den = 0.f;
    int c0 = lane * 2;
    int j = base;
    for (; j + 1 < end; j += 2) {
        int2 p0 = g_epack[j], p1 = g_epack[j + 1];
        float e0 = __expf(lrelu(g_s2[p0.x] + dd));
        float e1 = __expf(lrelu(g_s2[p1.x] + dd));
        unsigned u0 = *reinterpret_cast<const unsigned*>(&g_h2h[(size_t)p0.x * HID + c0]);
        unsigned u1 = *reinterpret_cast<const unsigned*>(&g_h2h[(size_t)p1.x * HID + c0]);
        float2 v0 = __half22float2(*reinterpret_cast<__half2*>(&u0));
        float2 v1 = __half22float2(*reinterpret_cast<__half2*>(&u1));
        den += e0 + e1;
        a0  += v0.x * e0 + v1.x * e1;
        a1v += v0.y * e0 + v1.y * e1;
    }
    if (j < end) {
        int2 p = g_epack[j];
        float e = __expf(lrelu(g_s2[p.x] + dd));
        unsigned u = *reinterpret_cast<const unsigned*>(&g_h2h[(size_t)p.x * HID + c0]);
        float2 v = __half22float2(*reinterpret_cast<__half2*>(&u));
        den += e; a0 += v.x * e; a1v += v.y * e;
    }
    float inv = 1.f / (den + EPS_SM);

    for (int jj = base + lane; jj < end; jj += 32) {
        int2 p = g_epack[jj];
        a2[p.y] = __expf(lrelu(g_s2[p.x] + dd)) * inv;
    }
    a0 *= inv; a1v *= inv;

    // +b2, LN(64), ELU
    a0  += b2[c0];
    a1v += b2[c0 + 1];
    float sum = wredsum(a0 + a1v);
    float sq  = wredsum(a0 * a0 + a1v * a1v);
    float mu  = sum * (1.f / 64.f);
    float var = sq * (1.f / 64.f) - mu * mu;
    float rs  = rsqrtf(var + 1e-5f);
    float y0 = eluf((a0  - mu) * rs * g2[c0]     + e2[c0]);
    float y1 = eluf((a1v - mu) * rs * g2[c0 + 1] + e2[c0 + 1]);
    zs[w][c0] = y0; zs[w][c0 + 1] = y1;
    __syncwarp();

    // MLP head: 64 -> 32 -> ReLU -> 1
    float acc = b1s[lane];
#pragma unroll
    for (int k = 0; k < 64; k++) acc += zs[w][k] * w1s[k * 32 + lane];
    acc = fmaxf(acc, 0.f);
    float p = wredsum(acc * w2s[lane]);
    if (lane == 0) out[n] = p + hb2[0];
}

// ------------------------- host launcher -------------------------------------
extern "C" void kernel_launch(void* const* d_in, const int* in_sizes, int n_in,
                              void* d_out, int out_size) {
    const float* x     = (const float*)d_in[0];
    const int*   ei    = (const int*)  d_in[1];
    const float* W1    = (const float*)d_in[2];
    const float* as1   = (const float*)d_in[3];
    const float* ad1   = (const float*)d_in[4];
    const float* b1    = (const float*)d_in[5];
    const float* W2    = (const float*)d_in[6];
    const float* as2   = (const float*)d_in[7];
    const float* ad2   = (const float*)d_in[8];
    const float* b2    = (const float*)d_in[9];
    const float* ln1g  = (const float*)d_in[10];
    const float* ln1b  = (const float*)d_in[11];
    const float* ln2g  = (const float*)d_in[12];
    const float* ln2b  = (const float*)d_in[13];
    const float* hW1   = (const float*)d_in[14];
    const float* hb1   = (const float*)d_in[15];
    const float* hW2   = (const float*)d_in[16];
    const float* hb2   = (const float*)d_in[17];
    float* out = (float*)d_out;

    // expected layout: out[N] | alpha1[ETOT*4] | alpha2[ETOT]
    size_t need = (size_t)N_NODES + (size_t)ETOT * (HEADS + 1);
    float *a1, *a2;
    if ((size_t)out_size >= need) {
        a1 = out + N_NODES;
        a2 = a1 + (size_t)ETOT * HEADS;
    } else {
        void* p;
        cudaGetSymbolAddress(&p, g_a1_fb); a1 = (float*)p;
        cudaGetSymbolAddress(&p, g_a2_fb); a2 = (float*)p;
    }

    auto cdiv = [](long a, long b) { return (int)((a + b - 1) / b); };

    __half *ph1, *ph2;
    float *px2, *ps1, *pd1, *ps2, *pd2;
    { void* p;
      cudaGetSymbolAddress(&p, g_h1h); ph1 = (__half*)p;
      cudaGetSymbolAddress(&p, g_x2);  px2 = (float*)p;
      cudaGetSymbolAddress(&p, g_h2h); ph2 = (__half*)p;
      cudaGetSymbolAddress(&p, g_s1);  ps1 = (float*)p;
      cudaGetSymbolAddress(&p, g_d1);  pd1 = (float*)p;
      cudaGetSymbolAddress(&p, g_s2);  ps2 = (float*)p;
      cudaGetSymbolAddress(&p, g_d2);  pd2 = (float*)p;
    }

    cudaFuncSetAttribute(gemm1_wmma_kernel,
                         cudaFuncAttributeMaxDynamicSharedMemorySize, G1_SMEM);

    // side stream for the CSR build (fork-join; both branches rejoin before agg1)
    cudaStream_t side;
    cudaStreamCreateWithFlags(&side, cudaStreamNonBlocking);
    cudaEvent_t evF, evJ;
    cudaEventCreateWithFlags(&evF, cudaEventDisableTiming);
    cudaEventCreateWithFlags(&evJ, cudaEventDisableTiming);

    cudaEventRecord(evF, 0);
    cudaStreamWaitEvent(side, evF, 0);

    // ---- CSR build on side stream (independent of GEMM1) ----
    zero_cnt_kernel<<<cdiv(N_PAD / 4, 256), 256, 0, side>>>();
    hist_kernel<<<cdiv(cdiv(ETOT, 4), 256), 256, 0, side>>>(ei);
    scan_kernel<<<1, SCAN_T, 0, side>>>();
    scatter_kernel<<<cdiv(cdiv(ETOT, 4), 256), 256, 0, side>>>(ei);
    cudaEventRecord(evJ, side);

    // ---- layer 1: W1->fp16, then HMMA GEMM + fused logits (main stream) ----
    conv_w1_kernel<<<cdiv(F_IN * C1 / 4, 256), 256>>>(W1);
    gemm1_wmma_kernel<<<cdiv(N_NODES, G1_BM), 256, G1_SMEM>>>(
        x, as1, ad1, ph1, ps1, pd1, N_NODES);

    cudaStreamWaitEvent(0, evJ, 0);     // join: agg1 needs CSR + h1 + s1/d1
    agg1_kernel<<<cdiv((long)N_NODES * 32, 256), 256>>>(a1, b1, ln1g, ln1b);

    // ---- layer 2 ----
    gemm_sd2_kernel<<<cdiv(N_NODES, 32), 128>>>(px2, W2, ph2, as2, ad2, ps2, pd2, N_NODES);
    agg2_kernel<<<cdiv(N_NODES, 8), 256>>>(a2, b2, ln2g, ln2b, hW1, hb1, hW2, hb2, out);
}

// round 10
// speedup vs baseline: 2.8187x; 1.1555x over previous
#include <cuda_runtime.h>
#include <cuda_fp16.h>
#include <mma.h>
#include <math.h>

using namespace nvcuda;

#define N_NODES 50000
#define E_EDGES 800000
#define ETOT    (E_EDGES + N_NODES)   // 850000
#define F_IN    128
#define HID     64
#define HEADS   4
#define C1      (HEADS * HID)         // 256
#define SLOPE   0.2f
#define EPS_SM  1e-16f

#define SCAN_T  1024
#define SCAN_CH 52                     // 52*1024 = 53248 >= N_NODES, /4
#define N_PAD   (SCAN_T * SCAN_CH)

// wmma gemm1 tiling
#define G1_BM    64
#define G1_ALD   136                   // padded half stride for A tile
#define G1_WLD   264                   // padded half stride for W tile
#define G1_SLD   264                   // padded float stride for stage
#define G1_SMEM  ((G1_BM * G1_ALD + 128 * G1_WLD) * 2 > G1_BM * G1_SLD * 4 ? \
                  (G1_BM * G1_ALD + 128 * G1_WLD) * 2 : G1_BM * G1_SLD * 4)

// wmma gemm2 tiling (64 rows x 64 cols x K=256, 4 warps)
#define G2_BM    64
#define G2_ALD   264                   // padded half stride for A (K=256)
#define G2_WLD   72                    // padded half stride for W (N=64)
#define G2_SLD   72                    // padded float stride for stage
#define G2_SMEM  ((G2_BM * G2_ALD + 256 * G2_WLD) * 2)   // 70656 B; stage aliases

// ------------------------- device scratch (no allocs allowed) ---------------
__device__ __half g_h1h[(size_t)N_NODES * C1];    // x @ W1 (fp16 storage)
__device__ float  g_x2 [(size_t)N_NODES * C1];    // layer1 output after LN/ELU (fp32)
__device__ __half g_h2h[(size_t)N_NODES * HID];   // x2 @ W2 (fp16 storage)
__device__ __half g_w1h[F_IN * C1];               // W1 pre-converted to fp16
__device__ __half g_w2h[C1 * HID];                // W2 pre-converted to fp16
__device__ float g_s1  [N_NODES * HEADS];
__device__ float g_d1  [N_NODES * HEADS];
__device__ float g_s2  [N_NODES];
__device__ float g_d2  [N_NODES];
// CSR by destination (rebuilt every launch; deterministic work)
__device__ __align__(16) int g_cnt   [N_PAD];
__device__ __align__(16) int g_rowptr[N_PAD + 4];
__device__ __align__(16) int g_wofs  [N_PAD + 4];
__device__ int2 g_epack[ETOT];                    // {src, eid} per CSR slot
// fallback alpha scratch in case d_out layout differs from expectation
__device__ float g_a1_fb[(size_t)ETOT * HEADS];
__device__ float g_a2_fb[(size_t)ETOT];

// ------------------------- helpers ------------------------------------------
__device__ __forceinline__ float lrelu(float v) { return v > 0.f ? v : SLOPE * v; }
__device__ __forceinline__ float eluf(float v)  { return v > 0.f ? v : expm1f(v); }

__device__ __forceinline__ float wredsum(float v) {
#pragma unroll
    for (int o = 16; o > 0; o >>= 1) v += __shfl_xor_sync(0xffffffffu, v, o);
    return v;
}

__device__ __forceinline__ uint2 pack_half4(float4 v) {
    __half2 h0 = __floats2half2_rn(v.x, v.y);
    __half2 h1 = __floats2half2_rn(v.z, v.w);
    return make_uint2(*reinterpret_cast<unsigned*>(&h0),
                      *reinterpret_cast<unsigned*>(&h1));
}

// ------------------------- CSR build -----------------------------------------
__global__ void zero_cnt_kernel() {
    int i = blockIdx.x * blockDim.x + threadIdx.x;
    if (i < N_PAD / 4) *reinterpret_cast<int4*>(&g_cnt[i * 4]) = make_int4(0, 0, 0, 0);
}

__global__ void hist_kernel(const int* __restrict__ ei) {
    int i0 = (blockIdx.x * blockDim.x + threadIdx.x) * 8;
    if (i0 >= ETOT) return;
    if (i0 + 8 <= E_EDGES) {
        int4 d0 = *reinterpret_cast<const int4*>(&ei[E_EDGES + i0]);
        int4 d1 = *reinterpret_cast<const int4*>(&ei[E_EDGES + i0 + 4]);
        atomicAdd(&g_cnt[d0.x], 1); atomicAdd(&g_cnt[d0.y], 1);
        atomicAdd(&g_cnt[d0.z], 1); atomicAdd(&g_cnt[d0.w], 1);
        atomicAdd(&g_cnt[d1.x], 1); atomicAdd(&g_cnt[d1.y], 1);
        atomicAdd(&g_cnt[d1.z], 1); atomicAdd(&g_cnt[d1.w], 1);
    } else {
#pragma unroll
        for (int t = 0; t < 8; t++) {
            int e = i0 + t;
            if (e < ETOT) {
                int dst = (e < E_EDGES) ? ei[E_EDGES + e] : e - E_EDGES;
                atomicAdd(&g_cnt[dst], 1);
            }
        }
    }
}

__global__ __launch_bounds__(SCAN_T) void scan_kernel() {
    __shared__ int sums[SCAN_T];
    int t = threadIdx.x;
    int lo = t * SCAN_CH;
    const int4* cp = reinterpret_cast<const int4*>(&g_cnt[lo]);
    int local = 0;
#pragma unroll
    for (int i = 0; i < SCAN_CH / 4; i++) {
        int4 c = cp[i];
        local += c.x + c.y + c.z + c.w;
    }
    sums[t] = local;
    __syncthreads();
    for (int off = 1; off < SCAN_T; off <<= 1) {
        int v = (t >= off) ? sums[t - off] : 0;
        __syncthreads();
        sums[t] += v;
        __syncthreads();
    }
    int run = sums[t] - local;                    // exclusive prefix
    int4* rp = reinterpret_cast<int4*>(&g_rowptr[lo]);
    int4* wp = reinterpret_cast<int4*>(&g_wofs[lo]);
#pragma unroll
    for (int i = 0; i < SCAN_CH / 4; i++) {
        int4 c = cp[i];
        int4 o;
        o.x = run; run += c.x;
        o.y = run; run += c.y;
        o.z = run; run += c.z;
        o.w = run; run += c.w;
        rp[i] = o; wp[i] = o;
    }
}

__global__ void scatter_kernel(const int* __restrict__ ei) {
    int i0 = (blockIdx.x * blockDim.x + threadIdx.x) * 8;
    if (i0 >= ETOT) return;
    if (i0 + 8 <= E_EDGES) {
        int4 s0 = *reinterpret_cast<const int4*>(&ei[i0]);
        int4 s1 = *reinterpret_cast<const int4*>(&ei[i0 + 4]);
        int4 d0 = *reinterpret_cast<const int4*>(&ei[E_EDGES + i0]);
        int4 d1 = *reinterpret_cast<const int4*>(&ei[E_EDGES + i0 + 4]);
        int sl;
        sl = atomicAdd(&g_wofs[d0.x], 1); g_epack[sl] = make_int2(s0.x, i0);
        sl = atomicAdd(&g_wofs[d0.y], 1); g_epack[sl] = make_int2(s0.y, i0 + 1);
        sl = atomicAdd(&g_wofs[d0.z], 1); g_epack[sl] = make_int2(s0.z, i0 + 2);
        sl = atomicAdd(&g_wofs[d0.w], 1); g_epack[sl] = make_int2(s0.w, i0 + 3);
        sl = atomicAdd(&g_wofs[d1.x], 1); g_epack[sl] = make_int2(s1.x, i0 + 4);
        sl = atomicAdd(&g_wofs[d1.y], 1); g_epack[sl] = make_int2(s1.y, i0 + 5);
        sl = atomicAdd(&g_wofs[d1.z], 1); g_epack[sl] = make_int2(s1.z, i0 + 6);
        sl = atomicAdd(&g_wofs[d1.w], 1); g_epack[sl] = make_int2(s1.w, i0 + 7);
    } else {
#pragma unroll
        for (int t = 0; t < 8; t++) {
            int e = i0 + t;
            if (e < ETOT) {
                int src, dst;
                if (e < E_EDGES) { src = ei[e]; dst = ei[E_EDGES + e]; }
                else             { src = dst = e - E_EDGES; }
                int slot = atomicAdd(&g_wofs[dst], 1);
                g_epack[slot] = make_int2(src, e);
            }
        }
    }
}

// ------------------------- W1+W2 fp32 -> fp16 (once per launch) --------------
__global__ void conv_w_kernel(const float* __restrict__ W1,
                              const float* __restrict__ W2) {
    int i4 = (blockIdx.x * blockDim.x + threadIdx.x) * 4;
    if (i4 < F_IN * C1) {
        float4 v = *reinterpret_cast<const float4*>(&W1[i4]);
        *reinterpret_cast<uint2*>(&g_w1h[i4]) = pack_half4(v);
    } else if (i4 < F_IN * C1 + C1 * HID) {
        int j4 = i4 - F_IN * C1;
        float4 v = *reinterpret_cast<const float4*>(&W2[j4]);
        *reinterpret_cast<uint2*>(&g_w2h[j4]) = pack_half4(v);
    }
}

// ---- layer-1 GEMM on tensor cores (HMMA) + fused logits ---------------------
__global__ __launch_bounds__(256)
void gemm1_wmma_kernel(const float* __restrict__ X,
                       const float* __restrict__ asrc, const float* __restrict__ adst,
                       __half* __restrict__ Yh,
                       float* __restrict__ S, float* __restrict__ D, int nrows) {
    extern __shared__ char smraw[];
    __half* Ah  = reinterpret_cast<__half*>(smraw);                      // [64][G1_ALD]
    __half* Wh  = reinterpret_cast<__half*>(smraw) + G1_BM * G1_ALD;     // [128][G1_WLD]
    float*  stg = reinterpret_cast<float*>(smraw);                       // [64][G1_SLD] aliased

    int tid = threadIdx.x;
    int rowbase = blockIdx.x * G1_BM;

    for (int i = tid * 4; i < G1_BM * F_IN; i += 256 * 4) {
        int r = i >> 7, c = i & 127;
        int gr = rowbase + r;
        float4 v = (gr < nrows) ? *reinterpret_cast<const float4*>(&X[(size_t)gr * F_IN + c])
                                : make_float4(0.f, 0.f, 0.f, 0.f);
        *reinterpret_cast<uint2*>(&Ah[r * G1_ALD + c]) = pack_half4(v);
    }
    for (int i = tid * 8; i < F_IN * C1; i += 256 * 8) {
        int k = i >> 8, c = i & 255;
        uint4 v = *reinterpret_cast<const uint4*>(&g_w1h[i]);
        *reinterpret_cast<uint4*>(&Wh[k * G1_WLD + c]) = v;
    }
    __syncthreads();

    int w = tid >> 5;
    int r0 = (w & 3) * 16;
    int cb = (w >> 2) * 128;

    wmma::fragment<wmma::accumulator, 16, 16, 16, float> acc[8];
#pragma unroll
    for (int f = 0; f < 8; f++) wmma::fill_fragment(acc[f], 0.f);

#pragma unroll
    for (int kk = 0; kk < F_IN; kk += 16) {
        wmma::fragment<wmma::matrix_a, 16, 16, 16, __half, wmma::row_major> af;
        wmma::load_matrix_sync(af, Ah + r0 * G1_ALD + kk, G1_ALD);
#pragma unroll
        for (int f = 0; f < 8; f++) {
            wmma::fragment<wmma::matrix_b, 16, 16, 16, __half, wmma::row_major> bf;
            wmma::load_matrix_sync(bf, Wh + kk * G1_WLD + cb + f * 16, G1_WLD);
            wmma::mma_sync(acc[f], af, bf, acc[f]);
        }
    }
    __syncthreads();
#pragma unroll
    for (int f = 0; f < 8; f++)
        wmma::store_matrix_sync(stg + r0 * G1_SLD + cb + f * 16, acc[f],
                                G1_SLD, wmma::mem_row_major);
    __syncthreads();

    int r = tid >> 2, q = tid & 3;
    int gr = rowbase + r;
    if (gr < nrows) {
        const float* as = asrc + q * 64;
        const float* ad = adst + q * 64;
        const float* row = stg + r * G1_SLD + q * 64;
        __half* yp = Yh + (size_t)gr * C1 + q * 64;
        float s = 0.f, dd = 0.f;
#pragma unroll
        for (int i = 0; i < 64; i += 4) {
            float4 v = *reinterpret_cast<const float4*>(&row[i]);
            float4 a = *reinterpret_cast<const float4*>(&as[i]);
            float4 b = *reinterpret_cast<const float4*>(&ad[i]);
            s  += v.x * a.x + v.y * a.y + v.z * a.z + v.w * a.w;
            dd += v.x * b.x + v.y * b.y + v.z * b.z + v.w * b.w;
            *reinterpret_cast<uint2*>(&yp[i]) = pack_half4(v);
        }
        S[gr * 4 + q] = s;
        D[gr * 4 + q] = dd;
    }
}

// ---- layer-2 GEMM on tensor cores (HMMA) + fused logits ---------------------
// block: 64 rows x 64 cols, K=256, 4 warps; A fp32->fp16 on load; W2 pre-conv.
__global__ __launch_bounds__(128)
void gemm2_wmma_kernel(const float* __restrict__ X,
                       const float* __restrict__ asrc, const float* __restrict__ adst,
                       __half* __restrict__ Yh,
                       float* __restrict__ S, float* __restrict__ D, int nrows) {
    extern __shared__ char smraw[];
    __half* Ah  = reinterpret_cast<__half*>(smraw);                      // [64][G2_ALD]
    __half* Wh  = reinterpret_cast<__half*>(smraw) + G2_BM * G2_ALD;     // [256][G2_WLD]
    float*  stg = reinterpret_cast<float*>(smraw);                       // [64][G2_SLD] aliased

    int tid = threadIdx.x;
    int rowbase = blockIdx.x * G2_BM;

    // A tile: 64 x 256 fp32 -> fp16
    for (int i = tid * 4; i < G2_BM * C1; i += 128 * 4) {
        int r = i >> 8, c = i & 255;
        int gr = rowbase + r;
        float4 v = (gr < nrows) ? *reinterpret_cast<const float4*>(&X[(size_t)gr * C1 + c])
                                : make_float4(0.f, 0.f, 0.f, 0.f);
        *reinterpret_cast<uint2*>(&Ah[r * G2_ALD + c]) = pack_half4(v);
    }
    // W tile: 256 x 64 fp16
    for (int i = tid * 8; i < C1 * HID; i += 128 * 8) {
        int k = i >> 6, c = i & 63;
        uint4 v = *reinterpret_cast<const uint4*>(&g_w2h[i]);
        *reinterpret_cast<uint4*>(&Wh[k * G2_WLD + c]) = v;
    }
    __syncthreads();

    int w = tid >> 5;
    int r0 = w * 16;                     // 4 warps x 16 rows

    wmma::fragment<wmma::accumulator, 16, 16, 16, float> acc[4];
#pragma unroll
    for (int f = 0; f < 4; f++) wmma::fill_fragment(acc[f], 0.f);

#pragma unroll
    for (int kk = 0; kk < C1; kk += 16) {
        wmma::fragment<wmma::matrix_a, 16, 16, 16, __half, wmma::row_major> af;
        wmma::load_matrix_sync(af, Ah + r0 * G2_ALD + kk, G2_ALD);
#pragma unroll
        for (int f = 0; f < 4; f++) {
            wmma::fragment<wmma::matrix_b, 16, 16, 16, __half, wmma::row_major> bf;
            wmma::load_matrix_sync(bf, Wh + kk * G2_WLD + f * 16, G2_WLD);
            wmma::mma_sync(acc[f], af, bf, acc[f]);
        }
    }
    __syncthreads();
#pragma unroll
    for (int f = 0; f < 4; f++)
        wmma::store_matrix_sync(stg + r0 * G2_SLD + f * 16, acc[f],
                                G2_SLD, wmma::mem_row_major);
    __syncthreads();

    // epilogue: thread -> (row, half); 32 cols each; pair-combine via shfl
    int r = tid >> 1, half = tid & 1;
    int c0 = half * 32;
    int gr = rowbase + r;
    float s = 0.f, dd = 0.f;
    if (gr < nrows) {
        const float* row = stg + r * G2_SLD + c0;
        __half* yp = Yh + (size_t)gr * HID + c0;
#pragma unroll
        for (int i = 0; i < 32; i += 4) {
            float4 v = *reinterpret_cast<const float4*>(&row[i]);
            float4 a = *reinterpret_cast<const float4*>(&asrc[c0 + i]);
            float4 b = *reinterpret_cast<const float4*>(&adst[c0 + i]);
            s  += v.x * a.x + v.y * a.y + v.z * a.z + v.w * a.w;
            dd += v.x * b.x + v.y * b.y + v.z * b.z + v.w * b.w;
            *reinterpret_cast<uint2*>(&yp[i]) = pack_half4(v);
        }
    }
    s  += __shfl_xor_sync(0xffffffffu, s, 1);
    dd += __shfl_xor_sync(0xffffffffu, dd, 1);
    if (gr < nrows && half == 0) { S[gr] = s; D[gr] = dd; }
}

// ------------------------- layer 1: single-pass gather + LN + ELU ------------
__global__ __launch_bounds__(256)
void agg1_kernel(float* __restrict__ a1, const float* __restrict__ b1,
                 const float* __restrict__ gam, const float* __restrict__ bet) {
    int n    = (blockIdx.x * blockDim.x + threadIdx.x) >> 5;
    int lane = threadIdx.x & 31;
    if (n >= N_NODES) return;
    int base = g_rowptr[n], end = g_rowptr[n + 1];
    float4 d = *reinterpret_cast<const float4*>(&g_d1[n * 4]);

    int h  = lane >> 3;           // head for this lane's 8-feature slice
    int c0 = lane * 8;
    float acc[8];
#pragma unroll
    for (int i = 0; i < 8; i++) acc[i] = 0.f;
    float4 den = make_float4(0.f, 0.f, 0.f, 0.f);

    int j = base;
    for (; j + 1 < end; j += 2) {
        int2 p0 = g_epack[j], p1 = g_epack[j + 1];
        int src0 = p0.x, src1 = p1.x;
        float4 s0 = *reinterpret_cast<const float4*>(&g_s1[src0 * 4]);
        float4 s1 = *reinterpret_cast<const float4*>(&g_s1[src1 * 4]);
        uint4 hv0 = *reinterpret_cast<const uint4*>(&g_h1h[(size_t)src0 * C1 + c0]);
        uint4 hv1 = *reinterpret_cast<const uint4*>(&g_h1h[(size_t)src1 * C1 + c0]);
        float4 e0, e1;
        e0.x = __expf(lrelu(s0.x + d.x)); e0.y = __expf(lrelu(s0.y + d.y));
        e0.z = __expf(lrelu(s0.z + d.z)); e0.w = __expf(lrelu(s0.w + d.w));
        e1.x = __expf(lrelu(s1.x + d.x)); e1.y = __expf(lrelu(s1.y + d.y));
        e1.z = __expf(lrelu(s1.z + d.z)); e1.w = __expf(lrelu(s1.w + d.w));
        den.x += e0.x + e1.x; den.y += e0.y + e1.y;
        den.z += e0.z + e1.z; den.w += e0.w + e1.w;
        float a0 = (h == 0) ? e0.x : (h == 1) ? e0.y : (h == 2) ? e0.z : e0.w;
        float a1w = (h == 0) ? e1.x : (h == 1) ? e1.y : (h == 2) ? e1.z : e1.w;
        float2 f00 = __half22float2(*reinterpret_cast<__half2*>(&hv0.x));
        float2 f01 = __half22float2(*reinterpret_cast<__half2*>(&hv0.y));
        float2 f02 = __half22float2(*reinterpret_cast<__half2*>(&hv0.z));
        float2 f03 = __half22float2(*reinterpret_cast<__half2*>(&hv0.w));
        float2 f10 = __half22float2(*reinterpret_cast<__half2*>(&hv1.x));
        float2 f11 = __half22float2(*reinterpret_cast<__half2*>(&hv1.y));
        float2 f12 = __half22float2(*reinterpret_cast<__half2*>(&hv1.z));
        float2 f13 = __half22float2(*reinterpret_cast<__half2*>(&hv1.w));
        acc[0] += f00.x * a0 + f10.x * a1w; acc[1] += f00.y * a0 + f10.y * a1w;
        acc[2] += f01.x * a0 + f11.x * a1w; acc[3] += f01.y * a0 + f11.y * a1w;
        acc[4] += f02.x * a0 + f12.x * a1w; acc[5] += f02.y * a0 + f12.y * a1w;
        acc[6] += f03.x * a0 + f13.x * a1w; acc[7] += f03.y * a0 + f13.y * a1w;
    }
    if (j < end) {
        int2 p = g_epack[j];
        int src = p.x;
        float4 s = *reinterpret_cast<const float4*>(&g_s1[src * 4]);
        float4 e;
        e.x = __expf(lrelu(s.x + d.x)); e.y = __expf(lrelu(s.y + d.y));
        e.z = __expf(lrelu(s.z + d.z)); e.w = __expf(lrelu(s.w + d.w));
        den.x += e.x; den.y += e.y; den.z += e.z; den.w += e.w;
        float a = (h == 0) ? e.x : (h == 1) ? e.y : (h == 2) ? e.z : e.w;
        uint4 hv = *reinterpret_cast<const uint4*>(&g_h1h[(size_t)src * C1 + c0]);
        float2 f0 = __half22float2(*reinterpret_cast<__half2*>(&hv.x));
        float2 f1 = __half22float2(*reinterpret_cast<__half2*>(&hv.y));
        float2 f2 = __half22float2(*reinterpret_cast<__half2*>(&hv.z));
        float2 f3 = __half22float2(*reinterpret_cast<__half2*>(&hv.w));
        acc[0] += f0.x * a; acc[1] += f0.y * a;
        acc[2] += f1.x * a; acc[3] += f1.y * a;
        acc[4] += f2.x * a; acc[5] += f2.y * a;
        acc[6] += f3.x * a; acc[7] += f3.y * a;
    }

    float4 inv = make_float4(1.f / (den.x + EPS_SM), 1.f / (den.y + EPS_SM),
                             1.f / (den.z + EPS_SM), 1.f / (den.w + EPS_SM));

    // alpha writes, lane-parallel
    for (int jj = base + lane; jj < end; jj += 32) {
        int2 p = g_epack[jj];
        float4 s = *reinterpret_cast<const float4*>(&g_s1[p.x * 4]);
        float4 al;
        al.x = __expf(lrelu(s.x + d.x)) * inv.x;
        al.y = __expf(lrelu(s.y + d.y)) * inv.y;
        al.z = __expf(lrelu(s.z + d.z)) * inv.z;
        al.w = __expf(lrelu(s.w + d.w)) * inv.w;
        *reinterpret_cast<float4*>(&a1[(size_t)p.y * 4]) = al;
    }

    float invh = (h == 0) ? inv.x : (h == 1) ? inv.y : (h == 2) ? inv.z : inv.w;
#pragma unroll
    for (int i = 0; i < 8; i++) acc[i] *= invh;

    // epilogue: +b1, LayerNorm(256), ELU -> g_x2
    float4 ba = *reinterpret_cast<const float4*>(&b1[c0]);
    float4 bb = *reinterpret_cast<const float4*>(&b1[c0 + 4]);
    acc[0] += ba.x; acc[1] += ba.y; acc[2] += ba.z; acc[3] += ba.w;
    acc[4] += bb.x; acc[5] += bb.y; acc[6] += bb.z; acc[7] += bb.w;
    float sum = 0.f, sq = 0.f;
#pragma unroll
    for (int i = 0; i < 8; i++) { sum += acc[i]; sq += acc[i] * acc[i]; }
    sum = wredsum(sum); sq = wredsum(sq);
    float mu  = sum * (1.f / 256.f);
    float var = sq * (1.f / 256.f) - mu * mu;
    float rs  = rsqrtf(var + 1e-5f);
    float4 ga = *reinterpret_cast<const float4*>(&gam[c0]);
    float4 gb = *reinterpret_cast<const float4*>(&gam[c0 + 4]);
    float4 ea = *reinterpret_cast<const float4*>(&bet[c0]);
    float4 eb = *reinterpret_cast<const float4*>(&bet[c0 + 4]);
    float4 y0, y1;
    y0.x = eluf((acc[0] - mu) * rs * ga.x + ea.x);
    y0.y = eluf((acc[1] - mu) * rs * ga.y + ea.y);
    y0.z = eluf((acc[2] - mu) * rs * ga.z + ea.z);
    y0.w = eluf((acc[3] - mu) * rs * ga.w + ea.w);
    y1.x = eluf((acc[4] - mu) * rs * gb.x + eb.x);
    y1.y = eluf((acc[5] - mu) * rs * gb.y + eb.y);
    y1.z = eluf((acc[6] - mu) * rs * gb.z + eb.z);
    y1.w = eluf((acc[7] - mu) * rs * gb.w + eb.w);
    float4* orow = reinterpret_cast<float4*>(&g_x2[(size_t)n * C1 + c0]);
    orow[0] = y0; orow[1] = y1;
}

// ------------------------- layer 2: single-pass gather + LN + ELU + head -----
__global__ __launch_bounds__(256)
void agg2_kernel(float* __restrict__ a2, const float* __restrict__ b2,
                 const float* __restrict__ g2, const float* __restrict__ e2,
                 const float* __restrict__ hW1, const float* __restrict__ hb1,
                 const float* __restrict__ hW2, const float* __restrict__ hb2,
                 float* __restrict__ out) {
    __shared__ float w1s[64 * 32];
    __shared__ float w2s[32];
    __shared__ float b1s[32];
    __shared__ float zs[8][64];
    int tid = threadIdx.x;
    for (int i = tid; i < 64 * 32; i += 256) w1s[i] = hW1[i];
    if (tid < 32) { w2s[tid] = hW2[tid]; b1s[tid] = hb1[tid]; }
    __syncthreads();

    int w    = tid >> 5;
    int lane = tid & 31;
    int n = blockIdx.x * 8 + w;
    if (n >= N_NODES) return;

    int base = g_rowptr[n], end = g_rowptr[n + 1];
    float dd = g_d2[n];

    float a0 = 0.f, a1v = 0.f, den = 0.f;
    int c0 = lane * 2;
    int j = base;
    for (; j + 1 < end; j += 2) {
        int2 p0 = g_epack[j], p1 = g_epack[j + 1];
        float e0 = __expf(lrelu(g_s2[p0.x] + dd));
        float e1 = __expf(lrelu(g_s2[p1.x] + dd));
        unsigned u0 = *reinterpret_cast<const unsigned*>(&g_h2h[(size_t)p0.x * HID + c0]);
        unsigned u1 = *reinterpret_cast<const unsigned*>(&g_h2h[(size_t)p1.x * HID + c0]);
        float2 v0 = __half22float2(*reinterpret_cast<__half2*>(&u0));
        float2 v1 = __half22float2(*reinterpret_cast<__half2*>(&u1));
        den += e0 + e1;
        a0  += v0.x * e0 + v1.x * e1;
        a1v += v0.y * e0 + v1.y * e1;
    }
    if (j < end) {
        int2 p = g_epack[j];
        float e = __expf(lrelu(g_s2[p.x] + dd));
        unsigned u = *reinterpret_cast<const unsigned*>(&g_h2h[(size_t)p.x * HID + c0]);
        float2 v = __half22float2(*reinterpret_cast<__half2*>(&u));
        den += e; a0 += v.x * e; a1v += v.y * e;
    }
    float inv = 1.f / (den + EPS_SM);

    for (int jj = base + lane; jj < end; jj += 32) {
        int2 p = g_epack[jj];
        a2[p.y] = __expf(lrelu(g_s2[p.x] + dd)) * inv;
    }
    a0 *= inv; a1v *= inv;

    // +b2, LN(64), ELU
    a0  += b2[c0];
    a1v += b2[c0 + 1];
    float sum = wredsum(a0 + a1v);
    float sq  = wredsum(a0 * a0 + a1v * a1v);
    float mu  = sum * (1.f / 64.f);
    float var = sq * (1.f / 64.f) - mu * mu;
    float rs  = rsqrtf(var + 1e-5f);
    float y0 = eluf((a0  - mu) * rs * g2[c0]     + e2[c0]);
    float y1 = eluf((a1v - mu) * rs * g2[c0 + 1] + e2[c0 + 1]);
    zs[w][c0] = y0; zs[w][c0 + 1] = y1;
    __syncwarp();

    // MLP head: 64 -> 32 -> ReLU -> 1
    float acc = b1s[lane];
#pragma unroll
    for (int k = 0; k < 64; k++) acc += zs[w][k] * w1s[k * 32 + lane];
    acc = fmaxf(acc, 0.f);
    float p = wredsum(acc * w2s[lane]);
    if (lane == 0) out[n] = p + hb2[0];
}

// ------------------------- host launcher -------------------------------------
extern "C" void kernel_launch(void* const* d_in, const int* in_sizes, int n_in,
                              void* d_out, int out_size) {
    const float* x     = (const float*)d_in[0];
    const int*   ei    = (const int*)  d_in[1];
    const float* W1    = (const float*)d_in[2];
    const float* as1   = (const float*)d_in[3];
    const float* ad1   = (const float*)d_in[4];
    const float* b1    = (const float*)d_in[5];
    const float* W2    = (const float*)d_in[6];
    const float* as2   = (const float*)d_in[7];
    const float* ad2   = (const float*)d_in[8];
    const float* b2    = (const float*)d_in[9];
    const float* ln1g  = (const float*)d_in[10];
    const float* ln1b  = (const float*)d_in[11];
    const float* ln2g  = (const float*)d_in[12];
    const float* ln2b  = (const float*)d_in[13];
    const float* hW1   = (const float*)d_in[14];
    const float* hb1   = (const float*)d_in[15];
    const float* hW2   = (const float*)d_in[16];
    const float* hb2   = (const float*)d_in[17];
    float* out = (float*)d_out;

    // expected layout: out[N] | alpha1[ETOT*4] | alpha2[ETOT]
    size_t need = (size_t)N_NODES + (size_t)ETOT * (HEADS + 1);
    float *a1, *a2;
    if ((size_t)out_size >= need) {
        a1 = out + N_NODES;
        a2 = a1 + (size_t)ETOT * HEADS;
    } else {
        void* p;
        cudaGetSymbolAddress(&p, g_a1_fb); a1 = (float*)p;
        cudaGetSymbolAddress(&p, g_a2_fb); a2 = (float*)p;
    }

    auto cdiv = [](long a, long b) { return (int)((a + b - 1) / b); };

    float *px2, *ps1, *pd1, *ps2, *pd2;
    __half *ph1, *ph2;
    { void* p;
      cudaGetSymbolAddress(&p, g_h1h); ph1 = (__half*)p;
      cudaGetSymbolAddress(&p, g_x2);  px2 = (float*)p;
      cudaGetSymbolAddress(&p, g_h2h); ph2 = (__half*)p;
      cudaGetSymbolAddress(&p, g_s1);  ps1 = (float*)p;
      cudaGetSymbolAddress(&p, g_d1);  pd1 = (float*)p;
      cudaGetSymbolAddress(&p, g_s2);  ps2 = (float*)p;
      cudaGetSymbolAddress(&p, g_d2);  pd2 = (float*)p;
    }

    cudaFuncSetAttribute(gemm1_wmma_kernel,
                         cudaFuncAttributeMaxDynamicSharedMemorySize, G1_SMEM);
    cudaFuncSetAttribute(gemm2_wmma_kernel,
                         cudaFuncAttributeMaxDynamicSharedMemorySize, G2_SMEM);

    // side stream for the CSR build (fork-join; both branches rejoin before agg1)
    cudaStream_t side;
    cudaStreamCreateWithFlags(&side, cudaStreamNonBlocking);
    cudaEvent_t evF, evJ;
    cudaEventCreateWithFlags(&evF, cudaEventDisableTiming);
    cudaEventCreateWithFlags(&evJ, cudaEventDisableTiming);

    cudaEventRecord(evF, 0);
    cudaStreamWaitEvent(side, evF, 0);

    // ---- CSR build on side stream (independent of GEMM1) ----
    zero_cnt_kernel<<<cdiv(N_PAD / 4, 256), 256, 0, side>>>();
    hist_kernel<<<cdiv(cdiv(ETOT, 8), 256), 256, 0, side>>>(ei);
    scan_kernel<<<1, SCAN_T, 0, side>>>();
    scatter_kernel<<<cdiv(cdiv(ETOT, 8), 256), 256, 0, side>>>(ei);
    cudaEventRecord(evJ, side);

    // ---- layer 1: W1/W2->fp16, then HMMA GEMM + fused logits (main stream) ----
    conv_w_kernel<<<cdiv((F_IN * C1 + C1 * HID) / 4, 256), 256>>>(W1, W2);
    gemm1_wmma_kernel<<<cdiv(N_NODES, G1_BM), 256, G1_SMEM>>>(
        x, as1, ad1, ph1, ps1, pd1, N_NODES);

    cudaStreamWaitEvent(0, evJ, 0);     // join: agg1 needs CSR + h1 + s1/d1
    agg1_kernel<<<cdiv((long)N_NODES * 32, 256), 256>>>(a1, b1, ln1g, ln1b);

    // ---- layer 2: HMMA GEMM + fused logits ----
    gemm2_wmma_kernel<<<cdiv(N_NODES, G2_BM), 128, G2_SMEM>>>(
        px2, as2, ad2, ph2, ps2, pd2, N_NODES);
    agg2_kernel<<<cdiv(N_NODES, 8), 256>>>(a2, b2, ln2g, ln2b, hW1, hb1, hW2, hb2, out);
}